// round 7
// baseline (speedup 1.0000x reference)
#include <cuda_runtime.h>
#include <cuda_bf16.h>

#define D      128
#define GATES  512
#define BATCH  64
#define NVAR   32
#define LSEQ   128
#define BSUB   16
#define PSPLIT 4

// recon: 64*127*32 = 260096 ; pred: 2048 @260096 ; C_star: 262144 @262144
#define RECON_SZ   260096
#define PRED_OFF   260096
#define CSTAR_OFF  262144

typedef unsigned long long u64;

// ---------------- device scratch (no allocation allowed) ----------------
__device__ __align__(16) float g_WtEnc[NVAR * D * GATES];   // [n][k][g]
__device__ __align__(16) float g_WtDec[NVAR * D * GATES];   // [n][k][g]
__device__ __align__(16) float g_WtIH [NVAR * D * D];       // [n][k][e]
__device__ __align__(16) float g_WtIC [NVAR * D * D];       // [n][k][e]
__device__ __align__(16) float g_WqkvT[D * 384];            // [k][j]
__device__ __align__(16) float g_C    [BATCH * NVAR * D];   // (B,N,D)
__device__ __align__(16) float g_Cstar[BATCH * NVAR * D];   // (B,N,D)

// ---------------- f32x2 helpers ----------------
__device__ __forceinline__ u64 ffma2(u64 a, u64 b, u64 c) {
    u64 d; asm("fma.rn.f32x2 %0, %1, %2, %3;" : "=l"(d) : "l"(a), "l"(b), "l"(c)); return d;
}
__device__ __forceinline__ u64 pack2(float lo, float hi) {
    u64 r; asm("mov.b64 %0, {%1, %2};" : "=l"(r) : "f"(lo), "f"(hi)); return r;
}
__device__ __forceinline__ void unpack2(u64 v, float& lo, float& hi) {
    asm("mov.b64 {%0, %1}, %2;" : "=f"(lo), "=f"(hi) : "l"(v));
}
__device__ __forceinline__ float fsig(float x)  { return __fdividef(1.f, 1.f + __expf(-x)); }
__device__ __forceinline__ float ftanhf(float x){ return 1.f - __fdividef(2.f, __expf(2.f * x) + 1.f); }

// ---------------- generic tiled transpose: src (batch,R,C) -> dst (batch,C,R) ----------------
__global__ void transpose_kernel(const float* __restrict__ src, float* __restrict__ dst,
                                 int R, int C) {
    __shared__ float tile[32][33];
    int n = blockIdx.z;
    src += (size_t)n * R * C;
    dst += (size_t)n * R * C;
    int c0 = blockIdx.x * 32, r0 = blockIdx.y * 32;
    #pragma unroll
    for (int i = threadIdx.y; i < 32; i += 8) {
        int r = r0 + i, c = c0 + threadIdx.x;
        tile[i][threadIdx.x] = src[r * C + c];
    }
    __syncthreads();
    #pragma unroll
    for (int i = threadIdx.y; i < 32; i += 8) {
        int c = c0 + i, r = r0 + threadIdx.x;
        dst[c * R + r] = tile[threadIdx.x][i];
    }
}

// ---------------- encoder: per (n, batch-quarter) CTA, 127 LSTM steps + online softmax pooling ----
// thread layout: lane -> u0 = 4*lane (4 units), warp -> rows b0 = 2*warp (2 rows)
__global__ __launch_bounds__(256, 1) void enc_kernel(
    const float* __restrict__ X,
    const float* __restrict__ Wih,
    const float* __restrict__ bih, const float* __restrict__ bhh,
    const float* __restrict__ pool_w, const float* __restrict__ pool_b) {
    const int n = blockIdx.y, p = blockIdx.x;
    const int tid = threadIdx.x, lane = tid & 31, warp = tid >> 5;
    const int u0 = lane * 4;
    const int b0 = warp * 2;

    __shared__ __align__(16) float h2[D][34];   // duplicated pairs: h2[k][2b] == h2[k][2b+1]

    for (int i = tid; i < D * 34; i += 256) ((float*)h2)[i] = 0.f;

    const float* Wt = g_WtEnc + (size_t)n * D * GATES;

    u64 bias2[4][2], wih2[4][2];
    #pragma unroll
    for (int gt = 0; gt < 4; gt++)
        #pragma unroll
        for (int up = 0; up < 2; up++) {
            int g = gt * 128 + u0 + 2 * up;
            bias2[gt][up] = pack2(bih[n * GATES + g]     + bhh[n * GATES + g],
                                  bih[n * GATES + g + 1] + bhh[n * GATES + g + 1]);
            wih2[gt][up]  = pack2(Wih[n * GATES + g], Wih[n * GATES + g + 1]);
        }
    float pw[4];
    #pragma unroll
    for (int uu = 0; uu < 4; uu++) pw[uu] = pool_w[n * D + u0 + uu];
    const float pb = pool_b[n];

    float c[4][2], accC[4][2];
    #pragma unroll
    for (int uu = 0; uu < 4; uu++)
        #pragma unroll
        for (int r = 0; r < 2; r++) { c[uu][r] = 0.f; accC[uu][r] = 0.f; }
    float m[2] = {-1e30f, -1e30f}, ssum[2] = {0.f, 0.f};

    __syncthreads();

    for (int t = 0; t < LSEQ - 1; t++) {
        float x0 = X[((p * BSUB + b0)     * LSEQ + t) * NVAR + n];
        float x1 = X[((p * BSUB + b0 + 1) * LSEQ + t) * NVAR + n];
        u64 xx0 = pack2(x0, x0), xx1 = pack2(x1, x1);

        u64 acc[4][2][2];
        #pragma unroll
        for (int gt = 0; gt < 4; gt++)
            #pragma unroll
            for (int up = 0; up < 2; up++) {
                acc[gt][up][0] = ffma2(wih2[gt][up], xx0, bias2[gt][up]);
                acc[gt][up][1] = ffma2(wih2[gt][up], xx1, bias2[gt][up]);
            }

        #pragma unroll 2
        for (int k = 0; k < D; k++) {
            u64 hd0 = *(const u64*)&h2[k][2 * b0];
            u64 hd1 = *(const u64*)&h2[k][2 * b0 + 2];
            const float* wrow = Wt + k * GATES + u0;
            #pragma unroll
            for (int gt = 0; gt < 4; gt++) {
                ulonglong2 w = *(const ulonglong2*)(wrow + gt * 128);
                acc[gt][0][0] = ffma2(w.x, hd0, acc[gt][0][0]);
                acc[gt][0][1] = ffma2(w.x, hd1, acc[gt][0][1]);
                acc[gt][1][0] = ffma2(w.y, hd0, acc[gt][1][0]);
                acc[gt][1][1] = ffma2(w.y, hd1, acc[gt][1][1]);
            }
        }

        float pre[4][4][2];
        #pragma unroll
        for (int gt = 0; gt < 4; gt++)
            #pragma unroll
            for (int up = 0; up < 2; up++)
                #pragma unroll
                for (int r = 0; r < 2; r++)
                    unpack2(acc[gt][up][r], pre[gt][2 * up][r], pre[gt][2 * up + 1][r]);

        float hn[4][2];
        #pragma unroll
        for (int uu = 0; uu < 4; uu++)
            #pragma unroll
            for (int r = 0; r < 2; r++) {
                float ig = fsig(pre[0][uu][r]);
                float fg = fsig(pre[1][uu][r]);
                float gg = ftanhf(pre[2][uu][r]);
                float og = fsig(pre[3][uu][r]);
                float cn = fg * c[uu][r] + ig * gg;
                c[uu][r] = cn;
                hn[uu][r] = og * ftanhf(cn);
            }

        // online softmax pooling over t — warp owns rows b0,b0+1 and all 128 units
        #pragma unroll
        for (int r = 0; r < 2; r++) {
            float ps = hn[0][r] * pw[0] + hn[1][r] * pw[1] + hn[2][r] * pw[2] + hn[3][r] * pw[3];
            #pragma unroll
            for (int off = 16; off > 0; off >>= 1) ps += __shfl_xor_sync(0xffffffffu, ps, off);
            float s = ps + pb;
            float mn = fmaxf(m[r], s);
            float scale = __expf(m[r] - mn);
            float wcur  = __expf(s - mn);
            ssum[r] = ssum[r] * scale + wcur;
            m[r] = mn;
            #pragma unroll
            for (int uu = 0; uu < 4; uu++)
                accC[uu][r] = accC[uu][r] * scale + wcur * hn[uu][r];
        }

        __syncthreads();
        #pragma unroll
        for (int uu = 0; uu < 4; uu++)
            #pragma unroll
            for (int r = 0; r < 2; r++)
                *(u64*)&h2[u0 + uu][2 * (b0 + r)] = pack2(hn[uu][r], hn[uu][r]);
        __syncthreads();
    }

    #pragma unroll
    for (int uu = 0; uu < 4; uu++)
        #pragma unroll
        for (int r = 0; r < 2; r++) {
            int b = p * BSUB + b0 + r;
            g_C[(b * NVAR + n) * D + u0 + uu] = accC[uu][r] / ssum[r];
        }
}

// ---------------- MHSA over the variable axis (tiny) ----------------
__global__ __launch_bounds__(128, 1) void mhsa_kernel(
    const float* __restrict__ bqkv,
    const float* __restrict__ Wo, const float* __restrict__ bo,
    float* __restrict__ out) {
    extern __shared__ __align__(16) float sm[];
    float* Cs  = sm;            // [128][34] duplicated-free, v-pairs adjacent
    float* QKV = sm + 4352;     // [32][385]
    float* As  = sm;            // [32][129] reuse region 1
    const int b = blockIdx.x, tid = threadIdx.x;

    #pragma unroll 4
    for (int i = 0; i < 32; i++)
        Cs[tid * 34 + i] = g_C[(b * NVAR + i) * D + tid];   // Cs[k][v]
    __syncthreads();

    // qkv = C @ Wqkv^T + bqkv  — f32x2 over v-pairs
    for (int jj = 0; jj < 3; jj++) {
        int j = jj * 128 + tid;
        float bj = bqkv[j];
        u64 acc[16];
        #pragma unroll
        for (int vp = 0; vp < 16; vp++) acc[vp] = pack2(bj, bj);
        #pragma unroll 2
        for (int k = 0; k < D; k++) {
            float w = g_WqkvT[k * 384 + j];
            u64 ww = pack2(w, w);
            const u64* crow = (const u64*)&Cs[k * 34];
            #pragma unroll
            for (int vp = 0; vp < 16; vp++) acc[vp] = ffma2(ww, crow[vp], acc[vp]);
        }
        #pragma unroll
        for (int vp = 0; vp < 16; vp++) {
            float a0, a1; unpack2(acc[vp], a0, a1);
            QKV[(2 * vp)     * 385 + j] = a0;
            QKV[(2 * vp + 1) * 385 + j] = a1;
        }
    }
    __syncthreads();

    // attention: thread = (head h, query var i)
    {
        int h = tid >> 5, i = tid & 31;
        float q[32];
        #pragma unroll
        for (int d = 0; d < 32; d++) q[d] = QKV[i * 385 + h * 32 + d];
        float s[32];
        #pragma unroll
        for (int j = 0; j < 32; j++) {
            float a = 0.f;
            #pragma unroll
            for (int d = 0; d < 32; d++) a += q[d] * QKV[j * 385 + 128 + h * 32 + d];
            s[j] = a * 0.17677669529663687f;   // 1/sqrt(32)
        }
        float mx = s[0];
        #pragma unroll
        for (int j = 1; j < 32; j++) mx = fmaxf(mx, s[j]);
        float sum = 0.f;
        #pragma unroll
        for (int j = 0; j < 32; j++) { s[j] = __expf(s[j] - mx); sum += s[j]; }
        float inv = __fdividef(1.f, sum);
        float A[32];
        #pragma unroll
        for (int d = 0; d < 32; d++) A[d] = 0.f;
        #pragma unroll
        for (int j = 0; j < 32; j++) {
            float aj = s[j] * inv;
            #pragma unroll
            for (int d = 0; d < 32; d++) A[d] += aj * QKV[j * 385 + 256 + h * 32 + d];
        }
        #pragma unroll
        for (int d = 0; d < 32; d++) As[i * 129 + h * 32 + d] = A[d];
    }
    __syncthreads();

    // out-proj: C_star = A @ Wo^T + bo
    {
        int v = tid & 31, uc = tid >> 5;
        for (int mm = 0; mm < 32; mm++) {
            int u = uc * 32 + mm;
            float a = bo[u];
            #pragma unroll 4
            for (int d = 0; d < D; d++) a += As[v * 129 + d] * Wo[u * D + d];
            g_Cstar[(b * NVAR + v) * D + u] = a;
            out[CSTAR_OFF + (b * NVAR + v) * D + u] = a;
        }
    }
}

// ---------------- decoder: init h,c from C_star, 128 LSTM steps + per-step out-projection ------
__global__ __launch_bounds__(256, 1) void dec_kernel(
    const float* __restrict__ ih_b, const float* __restrict__ ic_b,
    const float* __restrict__ bih,  const float* __restrict__ bhh,
    const float* __restrict__ out_w, const float* __restrict__ out_b,
    float* __restrict__ out) {
    const int n = blockIdx.y, p = blockIdx.x;
    const int tid = threadIdx.x, lane = tid & 31, warp = tid >> 5;
    const int u0 = lane * 4;
    const int b0 = warp * 2;

    __shared__ __align__(16) float h2[D][34];

    // stage cs = C_star (this block's 16 rows), duplicated
    #pragma unroll
    for (int i = 0; i < 8; i++) {
        int idx = i * 256 + tid;
        int r = idx >> 7, k = idx & 127;
        float v = g_Cstar[((p * BSUB + r) * NVAR + n) * D + k];
        h2[k][2 * r] = v; h2[k][2 * r + 1] = v;
    }

    u64 bias2[4][2];
    #pragma unroll
    for (int gt = 0; gt < 4; gt++)
        #pragma unroll
        for (int up = 0; up < 2; up++) {
            int g = gt * 128 + u0 + 2 * up;
            bias2[gt][up] = pack2(bih[n * GATES + g]     + bhh[n * GATES + g],
                                  bih[n * GATES + g + 1] + bhh[n * GATES + g + 1]);
        }
    float wout[4];
    #pragma unroll
    for (int uu = 0; uu < 4; uu++) wout[uu] = out_w[n * D + u0 + uu];
    const float ob = out_b[n];

    __syncthreads();

    // init matvecs: h = tanh(cs @ ihW^T + ihb), c = tanh(cs @ icW^T + icb)
    const float* WtIH = g_WtIH + (size_t)n * D * D;
    const float* WtIC = g_WtIC + (size_t)n * D * D;
    u64 ah[2][2], ac[2][2];
    #pragma unroll
    for (int up = 0; up < 2; up++) {
        int e = u0 + 2 * up;
        u64 bh = pack2(ih_b[n * D + e], ih_b[n * D + e + 1]);
        u64 bc = pack2(ic_b[n * D + e], ic_b[n * D + e + 1]);
        ah[up][0] = bh; ah[up][1] = bh;
        ac[up][0] = bc; ac[up][1] = bc;
    }
    #pragma unroll 2
    for (int k = 0; k < D; k++) {
        u64 hd0 = *(const u64*)&h2[k][2 * b0];
        u64 hd1 = *(const u64*)&h2[k][2 * b0 + 2];
        ulonglong2 wh = *(const ulonglong2*)(WtIH + k * D + u0);
        ulonglong2 wc = *(const ulonglong2*)(WtIC + k * D + u0);
        ah[0][0] = ffma2(wh.x, hd0, ah[0][0]); ah[0][1] = ffma2(wh.x, hd1, ah[0][1]);
        ah[1][0] = ffma2(wh.y, hd0, ah[1][0]); ah[1][1] = ffma2(wh.y, hd1, ah[1][1]);
        ac[0][0] = ffma2(wc.x, hd0, ac[0][0]); ac[0][1] = ffma2(wc.x, hd1, ac[0][1]);
        ac[1][0] = ffma2(wc.y, hd0, ac[1][0]); ac[1][1] = ffma2(wc.y, hd1, ac[1][1]);
    }
    float hn[4][2], c[4][2];
    #pragma unroll
    for (int up = 0; up < 2; up++)
        #pragma unroll
        for (int r = 0; r < 2; r++) {
            float a0, a1; unpack2(ah[up][r], a0, a1);
            hn[2 * up][r] = ftanhf(a0); hn[2 * up + 1][r] = ftanhf(a1);
            unpack2(ac[up][r], a0, a1);
            c[2 * up][r] = ftanhf(a0); c[2 * up + 1][r] = ftanhf(a1);
        }

    __syncthreads();
    #pragma unroll
    for (int uu = 0; uu < 4; uu++)
        #pragma unroll
        for (int r = 0; r < 2; r++)
            *(u64*)&h2[u0 + uu][2 * (b0 + r)] = pack2(hn[uu][r], hn[uu][r]);
    __syncthreads();

    const float* Wt = g_WtDec + (size_t)n * D * GATES;

    for (int l = 0; l < LSEQ; l++) {
        u64 acc[4][2][2];
        #pragma unroll
        for (int gt = 0; gt < 4; gt++)
            #pragma unroll
            for (int up = 0; up < 2; up++) {
                acc[gt][up][0] = bias2[gt][up];
                acc[gt][up][1] = bias2[gt][up];
            }

        #pragma unroll 2
        for (int k = 0; k < D; k++) {
            u64 hd0 = *(const u64*)&h2[k][2 * b0];
            u64 hd1 = *(const u64*)&h2[k][2 * b0 + 2];
            const float* wrow = Wt + k * GATES + u0;
            #pragma unroll
            for (int gt = 0; gt < 4; gt++) {
                ulonglong2 w = *(const ulonglong2*)(wrow + gt * 128);
                acc[gt][0][0] = ffma2(w.x, hd0, acc[gt][0][0]);
                acc[gt][0][1] = ffma2(w.x, hd1, acc[gt][0][1]);
                acc[gt][1][0] = ffma2(w.y, hd0, acc[gt][1][0]);
                acc[gt][1][1] = ffma2(w.y, hd1, acc[gt][1][1]);
            }
        }

        float pre[4][4][2];
        #pragma unroll
        for (int gt = 0; gt < 4; gt++)
            #pragma unroll
            for (int up = 0; up < 2; up++)
                #pragma unroll
                for (int r = 0; r < 2; r++)
                    unpack2(acc[gt][up][r], pre[gt][2 * up][r], pre[gt][2 * up + 1][r]);

        #pragma unroll
        for (int uu = 0; uu < 4; uu++)
            #pragma unroll
            for (int r = 0; r < 2; r++) {
                float ig = fsig(pre[0][uu][r]);
                float fg = fsig(pre[1][uu][r]);
                float gg = ftanhf(pre[2][uu][r]);
                float og = fsig(pre[3][uu][r]);
                float cn = fg * c[uu][r] + ig * gg;
                c[uu][r] = cn;
                hn[uu][r] = og * ftanhf(cn);
            }

        // output projection O[l,n,b] — warp butterfly over the 128 units
        #pragma unroll
        for (int r = 0; r < 2; r++) {
            float ps = hn[0][r] * wout[0] + hn[1][r] * wout[1] + hn[2][r] * wout[2] + hn[3][r] * wout[3];
            #pragma unroll
            for (int off = 16; off > 0; off >>= 1) ps += __shfl_xor_sync(0xffffffffu, ps, off);
            if (lane == 0) {
                float O = ps + ob;
                int b = p * BSUB + b0 + r;
                if (l < LSEQ - 1) out[(b * (LSEQ - 1) + l) * NVAR + n] = O;  // recon[b][l][n]
                else              out[PRED_OFF + b * NVAR + n] = O;          // pred[b][n]
            }
        }

        __syncthreads();
        #pragma unroll
        for (int uu = 0; uu < 4; uu++)
            #pragma unroll
            for (int r = 0; r < 2; r++)
                *(u64*)&h2[u0 + uu][2 * (b0 + r)] = pack2(hn[uu][r], hn[uu][r]);
        __syncthreads();
    }
}

// ---------------- launch ----------------
extern "C" void kernel_launch(void* const* d_in, const int* in_sizes, int n_in,
                              void* d_out, int out_size) {
    (void)in_sizes; (void)n_in; (void)out_size;
    const float* X        = (const float*)d_in[0];
    const float* enc_Wih  = (const float*)d_in[1];
    const float* enc_Whh  = (const float*)d_in[2];
    const float* enc_bih  = (const float*)d_in[3];
    const float* enc_bhh  = (const float*)d_in[4];
    const float* pool_w   = (const float*)d_in[5];
    const float* pool_b   = (const float*)d_in[6];
    const float* Wqkv     = (const float*)d_in[7];
    const float* bqkv     = (const float*)d_in[8];
    const float* Wo       = (const float*)d_in[9];
    const float* bo       = (const float*)d_in[10];
    const float* dec_ih_W = (const float*)d_in[11];
    const float* dec_ih_b = (const float*)d_in[12];
    const float* dec_ic_W = (const float*)d_in[13];
    const float* dec_ic_b = (const float*)d_in[14];
    /* d_in[15] dec_Wih unused (decoder input is zeros) */
    const float* dec_Whh  = (const float*)d_in[16];
    const float* dec_bih  = (const float*)d_in[17];
    const float* dec_bhh  = (const float*)d_in[18];
    const float* dec_out_W= (const float*)d_in[19];
    const float* dec_out_b= (const float*)d_in[20];
    float* out = (float*)d_out;

    static int smem_set = 0;
    if (!smem_set) {
        cudaFuncSetAttribute(mhsa_kernel, cudaFuncAttributeMaxDynamicSharedMemorySize, 66688);
        smem_set = 1;
    }

    float *pWtEnc, *pWtDec, *pWtIH, *pWtIC, *pWqkvT;
    cudaGetSymbolAddress((void**)&pWtEnc, g_WtEnc);
    cudaGetSymbolAddress((void**)&pWtDec, g_WtDec);
    cudaGetSymbolAddress((void**)&pWtIH,  g_WtIH);
    cudaGetSymbolAddress((void**)&pWtIC,  g_WtIC);
    cudaGetSymbolAddress((void**)&pWqkvT, g_WqkvT);

    dim3 tb(32, 8);
    transpose_kernel<<<dim3(4, 16, 32), tb>>>(enc_Whh,  pWtEnc, 512, 128);
    transpose_kernel<<<dim3(4, 16, 32), tb>>>(dec_Whh,  pWtDec, 512, 128);
    transpose_kernel<<<dim3(4,  4, 32), tb>>>(dec_ih_W, pWtIH,  128, 128);
    transpose_kernel<<<dim3(4,  4, 32), tb>>>(dec_ic_W, pWtIC,  128, 128);
    transpose_kernel<<<dim3(4, 12,  1), tb>>>(Wqkv,     pWqkvT, 384, 128);

    enc_kernel<<<dim3(PSPLIT, NVAR), 256>>>(X, enc_Wih, enc_bih, enc_bhh, pool_w, pool_b);
    mhsa_kernel<<<BATCH, 128, 66688>>>(bqkv, Wo, bo, out);
    dec_kernel<<<dim3(PSPLIT, NVAR), 256>>>(dec_ih_b, dec_ic_b, dec_bih, dec_bhh,
                                            dec_out_W, dec_out_b, out);
}

// round 8
// speedup vs baseline: 1.6289x; 1.6289x over previous
#include <cuda_runtime.h>
#include <cuda_bf16.h>

#define D      128
#define GATES  512
#define BATCH  64
#define NVAR   32
#define LSEQ   128
#define BSUB   16
#define PSPLIT 4
#define KT     32                      // k-rows per weight tile
#define NT     (D / KT)                // 4 tiles per step
#define TILE_F (KT * GATES)            // 16384 floats = 64KB

#define RECON_SZ   260096
#define PRED_OFF   260096
#define CSTAR_OFF  262144

typedef unsigned long long u64;

// ---------------- device scratch ----------------
__device__ __align__(16) float g_WtEnc[NVAR * D * GATES];   // [n][k][g]
__device__ __align__(16) float g_WtDec[NVAR * D * GATES];   // [n][k][g]
__device__ __align__(16) float g_WtIH [NVAR * D * D];       // [n][k][e]
__device__ __align__(16) float g_WtIC [NVAR * D * D];       // [n][k][e]
__device__ __align__(16) float g_WqkvT[D * 384];            // [k][j]
__device__ __align__(16) float g_C    [BATCH * NVAR * D];   // (B,N,D)
__device__ __align__(16) float g_Cstar[BATCH * NVAR * D];   // (B,N,D)

// ---------------- helpers ----------------
__device__ __forceinline__ u64 ffma2(u64 a, u64 b, u64 c) {
    u64 d; asm("fma.rn.f32x2 %0, %1, %2, %3;" : "=l"(d) : "l"(a), "l"(b), "l"(c)); return d;
}
__device__ __forceinline__ u64 pack2(float lo, float hi) {
    u64 r; asm("mov.b64 %0, {%1, %2};" : "=l"(r) : "f"(lo), "f"(hi)); return r;
}
__device__ __forceinline__ void unpack2(u64 v, float& lo, float& hi) {
    asm("mov.b64 {%0, %1}, %2;" : "=f"(lo), "=f"(hi) : "l"(v));
}
__device__ __forceinline__ float fsig(float x)  { return __fdividef(1.f, 1.f + __expf(-x)); }
__device__ __forceinline__ float ftanhf(float x){ return 1.f - __fdividef(2.f, __expf(2.f * x) + 1.f); }

__device__ __forceinline__ unsigned smem_u32(const void* p) {
    return (unsigned)__cvta_generic_to_shared(p);
}

// issue one 64KB weight tile: 256 threads x 16 x 16B cp.async, one commit group
__device__ __forceinline__ void issue_tile(const float* gsrc, float* sdst, int tid) {
    unsigned s = smem_u32(sdst) + tid * 16;
    const char* g = (const char*)gsrc + tid * 16;
    #pragma unroll
    for (int j = 0; j < 16; j++) {
        asm volatile("cp.async.cg.shared.global [%0], [%1], 16;"
                     :: "r"(s + j * 4096), "l"(g + j * 4096));
    }
    asm volatile("cp.async.commit_group;");
}

struct __align__(16) SmemLSTM {
    float wbuf[2][TILE_F];   // 131072 B
    float h2[D][34];         // 17408 B  duplicated pairs h2[k][2r]==h2[k][2r+1]
    float sbias[GATES];      // 2048 B
    float swih[GATES];       // 2048 B
    float sp[8][16];         // warp partials
    float sc[16][2];         // (scale, wcur) per row
    float sinv[16];
};
#define SMEM_BYTES ((int)sizeof(SmemLSTM))

// ---------------- transpose: src (batch,R,C) -> dst (batch,C,R) ----------------
__global__ void transpose_kernel(const float* __restrict__ src, float* __restrict__ dst,
                                 int R, int C) {
    __shared__ float tile[32][33];
    int n = blockIdx.z;
    src += (size_t)n * R * C;
    dst += (size_t)n * R * C;
    int c0 = blockIdx.x * 32, r0 = blockIdx.y * 32;
    #pragma unroll
    for (int i = threadIdx.y; i < 32; i += 8)
        tile[i][threadIdx.x] = src[(r0 + i) * C + c0 + threadIdx.x];
    __syncthreads();
    #pragma unroll
    for (int i = threadIdx.y; i < 32; i += 8)
        dst[(c0 + i) * R + r0 + threadIdx.x] = tile[threadIdx.x][i];
}

// ================= encoder =================
// mapping: warp w owns units [16w,16w+16); lane: gh=lane>>4 picks 8-unit half, r=lane&15 = row
__global__ __launch_bounds__(256, 1) void enc_kernel(
    const float* __restrict__ X,
    const float* __restrict__ Wih,
    const float* __restrict__ bih, const float* __restrict__ bhh,
    const float* __restrict__ pool_w, const float* __restrict__ pool_b) {
    extern __shared__ __align__(16) char smraw[];
    SmemLSTM* sm = (SmemLSTM*)smraw;
    const int n = blockIdx.y, p = blockIdx.x;
    const int tid = threadIdx.x, lane = tid & 31, w = tid >> 5;
    const int gh = lane >> 4, r = lane & 15;
    const int u0 = 16 * w + 8 * gh;
    const int b_row = p * BSUB + r;

    for (int i = tid; i < GATES; i += 256) {
        sm->sbias[i] = bih[n * GATES + i] + bhh[n * GATES + i];
        sm->swih[i]  = Wih[n * GATES + i];
    }
    for (int i = tid; i < D * 34; i += 256) ((float*)sm->h2)[i] = 0.f;
    __syncthreads();

    const float* Wt = g_WtEnc + (size_t)n * D * GATES;
    issue_tile(Wt + 0 * TILE_F, sm->wbuf[0], tid);
    issue_tile(Wt + 1 * TILE_F, sm->wbuf[1], tid);

    float c[8], accC[8], hn[8], pw8[8];
    #pragma unroll
    for (int j = 0; j < 8; j++) {
        c[j] = 0.f; accC[j] = 0.f;
        pw8[j] = pool_w[n * D + u0 + j];
    }
    const float pb = pool_b[n];
    float pm = -1e30f, pss = 0.f;   // valid in warp0/gh0 lanes only

    float xcur = X[(b_row * LSEQ + 0) * NVAR + n];

    for (int t = 0; t < LSEQ - 1; t++) {
        // acc init: bias + wih * x
        u64 acc[4][4];
        u64 xx = pack2(xcur, xcur);
        #pragma unroll
        for (int t4 = 0; t4 < 4; t4++) {
            int g0 = t4 * 128 + u0;
            ulonglong2 b0 = *(const ulonglong2*)&sm->sbias[g0];
            ulonglong2 b1 = *(const ulonglong2*)&sm->sbias[g0 + 4];
            ulonglong2 w0 = *(const ulonglong2*)&sm->swih[g0];
            ulonglong2 w1 = *(const ulonglong2*)&sm->swih[g0 + 4];
            acc[t4][0] = ffma2(w0.x, xx, b0.x);
            acc[t4][1] = ffma2(w0.y, xx, b0.y);
            acc[t4][2] = ffma2(w1.x, xx, b1.x);
            acc[t4][3] = ffma2(w1.y, xx, b1.y);
        }
        float xnext = X[(b_row * LSEQ + t + 1) * NVAR + n];

        #pragma unroll
        for (int kt = 0; kt < NT; kt++) {
            asm volatile("cp.async.wait_group 1;");
            __syncthreads();
            const float* wb = sm->wbuf[kt & 1];
            #pragma unroll 4
            for (int kk = 0; kk < KT; kk++) {
                int k = kt * KT + kk;
                u64 hh = *(const u64*)&sm->h2[k][2 * r];
                const float* wrow = wb + kk * GATES + u0;
                #pragma unroll
                for (int t4 = 0; t4 < 4; t4++) {
                    ulonglong2 wA = *(const ulonglong2*)(wrow + t4 * 128);
                    ulonglong2 wB = *(const ulonglong2*)(wrow + t4 * 128 + 4);
                    acc[t4][0] = ffma2(wA.x, hh, acc[t4][0]);
                    acc[t4][1] = ffma2(wA.y, hh, acc[t4][1]);
                    acc[t4][2] = ffma2(wB.x, hh, acc[t4][2]);
                    acc[t4][3] = ffma2(wB.y, hh, acc[t4][3]);
                }
            }
            __syncthreads();
            issue_tile(Wt + ((kt + 2) & 3) * TILE_F, sm->wbuf[kt & 1], tid);
        }

        // nonlinearity
        #pragma unroll
        for (int pp = 0; pp < 4; pp++) {
            float i0, i1, f0, f1, g0, g1, o0, o1;
            unpack2(acc[0][pp], i0, i1);
            unpack2(acc[1][pp], f0, f1);
            unpack2(acc[2][pp], g0, g1);
            unpack2(acc[3][pp], o0, o1);
            int j = 2 * pp;
            c[j]     = fsig(f0) * c[j]     + fsig(i0) * ftanhf(g0);
            hn[j]    = fsig(o0) * ftanhf(c[j]);
            c[j + 1] = fsig(f1) * c[j + 1] + fsig(i1) * ftanhf(g1);
            hn[j + 1]= fsig(o1) * ftanhf(c[j + 1]);
        }

        // pooling partial + h2 write
        float part = 0.f;
        #pragma unroll
        for (int j = 0; j < 8; j++) part += hn[j] * pw8[j];
        part += __shfl_xor_sync(0xffffffffu, part, 16);
        #pragma unroll
        for (int j = 0; j < 8; j++)
            *(u64*)&sm->h2[u0 + j][2 * r] = pack2(hn[j], hn[j]);
        if (gh == 0) sm->sp[w][r] = part;
        __syncthreads();
        if (w == 0 && gh == 0) {
            float s = pb;
            #pragma unroll
            for (int ww = 0; ww < 8; ww++) s += sm->sp[ww][r];
            float mn = fmaxf(pm, s);
            float scale = __expf(pm - mn);
            float wcur  = __expf(s - mn);
            pss = pss * scale + wcur;
            pm = mn;
            sm->sc[r][0] = scale; sm->sc[r][1] = wcur;
        }
        __syncthreads();
        float s0 = sm->sc[r][0], w0v = sm->sc[r][1];
        #pragma unroll
        for (int j = 0; j < 8; j++) accC[j] = accC[j] * s0 + w0v * hn[j];
        xcur = xnext;
    }
    asm volatile("cp.async.wait_group 0;");
    if (w == 0 && gh == 0) sm->sinv[r] = __fdividef(1.f, pss);
    __syncthreads();
    float iv = sm->sinv[r];
    #pragma unroll
    for (int j = 0; j < 8; j++)
        g_C[(b_row * NVAR + n) * D + u0 + j] = accC[j] * iv;
}

// ================= MHSA (unchanged) =================
__global__ __launch_bounds__(128, 1) void mhsa_kernel(
    const float* __restrict__ bqkv,
    const float* __restrict__ Wo, const float* __restrict__ bo,
    float* __restrict__ out) {
    extern __shared__ __align__(16) float smf[];
    float* Cs  = smf;            // [128][34]
    float* QKV = smf + 4352;     // [32][385]
    float* As  = smf;            // [32][129] reuse
    const int b = blockIdx.x, tid = threadIdx.x;

    #pragma unroll 4
    for (int i = 0; i < 32; i++)
        Cs[tid * 34 + i] = g_C[(b * NVAR + i) * D + tid];
    __syncthreads();

    for (int jj = 0; jj < 3; jj++) {
        int j = jj * 128 + tid;
        float bj = bqkv[j];
        u64 acc[16];
        #pragma unroll
        for (int vp = 0; vp < 16; vp++) acc[vp] = pack2(bj, bj);
        #pragma unroll 2
        for (int k = 0; k < D; k++) {
            float wv = g_WqkvT[k * 384 + j];
            u64 ww = pack2(wv, wv);
            const u64* crow = (const u64*)&Cs[k * 34];
            #pragma unroll
            for (int vp = 0; vp < 16; vp++) acc[vp] = ffma2(ww, crow[vp], acc[vp]);
        }
        #pragma unroll
        for (int vp = 0; vp < 16; vp++) {
            float a0, a1; unpack2(acc[vp], a0, a1);
            QKV[(2 * vp)     * 385 + j] = a0;
            QKV[(2 * vp + 1) * 385 + j] = a1;
        }
    }
    __syncthreads();

    {
        int h = tid >> 5, i = tid & 31;
        float q[32];
        #pragma unroll
        for (int d = 0; d < 32; d++) q[d] = QKV[i * 385 + h * 32 + d];
        float s[32];
        #pragma unroll
        for (int j = 0; j < 32; j++) {
            float a = 0.f;
            #pragma unroll
            for (int d = 0; d < 32; d++) a += q[d] * QKV[j * 385 + 128 + h * 32 + d];
            s[j] = a * 0.17677669529663687f;
        }
        float mx = s[0];
        #pragma unroll
        for (int j = 1; j < 32; j++) mx = fmaxf(mx, s[j]);
        float sum = 0.f;
        #pragma unroll
        for (int j = 0; j < 32; j++) { s[j] = __expf(s[j] - mx); sum += s[j]; }
        float inv = __fdividef(1.f, sum);
        float A[32];
        #pragma unroll
        for (int d = 0; d < 32; d++) A[d] = 0.f;
        #pragma unroll
        for (int j = 0; j < 32; j++) {
            float aj = s[j] * inv;
            #pragma unroll
            for (int d = 0; d < 32; d++) A[d] += aj * QKV[j * 385 + 256 + h * 32 + d];
        }
        #pragma unroll
        for (int d = 0; d < 32; d++) As[i * 129 + h * 32 + d] = A[d];
    }
    __syncthreads();

    {
        int v = tid & 31, uc = tid >> 5;
        for (int mm = 0; mm < 32; mm++) {
            int u = uc * 32 + mm;
            float a = bo[u];
            #pragma unroll 4
            for (int d = 0; d < D; d++) a += As[v * 129 + d] * Wo[u * D + d];
            g_Cstar[(b * NVAR + v) * D + u] = a;
            out[CSTAR_OFF + (b * NVAR + v) * D + u] = a;
        }
    }
}

// ================= decoder =================
__global__ __launch_bounds__(256, 1) void dec_kernel(
    const float* __restrict__ ih_b, const float* __restrict__ ic_b,
    const float* __restrict__ bih,  const float* __restrict__ bhh,
    const float* __restrict__ out_w, const float* __restrict__ out_b,
    float* __restrict__ out) {
    extern __shared__ __align__(16) char smraw[];
    SmemLSTM* sm = (SmemLSTM*)smraw;
    const int n = blockIdx.y, p = blockIdx.x;
    const int tid = threadIdx.x, lane = tid & 31, w = tid >> 5;
    const int gh = lane >> 4, r = lane & 15;
    const int u0 = 16 * w + 8 * gh;
    const int b_row = p * BSUB + r;

    for (int i = tid; i < GATES; i += 256)
        sm->sbias[i] = bih[n * GATES + i] + bhh[n * GATES + i];
    // stage C_star rows into h2 (duplicated pairs)
    #pragma unroll
    for (int i = 0; i < 8; i++) {
        int idx = i * 256 + tid;
        int rr = idx >> 7, k = idx & 127;
        float v = g_Cstar[((p * BSUB + rr) * NVAR + n) * D + k];
        sm->h2[k][2 * rr] = v; sm->h2[k][2 * rr + 1] = v;
    }
    __syncthreads();

    const float* Wt = g_WtDec + (size_t)n * D * GATES;
    issue_tile(Wt + 0 * TILE_F, sm->wbuf[0], tid);
    issue_tile(Wt + 1 * TILE_F, sm->wbuf[1], tid);

    // init matvecs (overlapped with cp.async)
    const float* WtIH = g_WtIH + (size_t)n * D * D;
    const float* WtIC = g_WtIC + (size_t)n * D * D;
    u64 ah[4], ac4[4];
    #pragma unroll
    for (int pp = 0; pp < 4; pp++) {
        int e = u0 + 2 * pp;
        ah[pp]  = pack2(ih_b[n * D + e], ih_b[n * D + e + 1]);
        ac4[pp] = pack2(ic_b[n * D + e], ic_b[n * D + e + 1]);
    }
    #pragma unroll 2
    for (int k = 0; k < D; k++) {
        u64 hh = *(const u64*)&sm->h2[k][2 * r];
        ulonglong2 whA = *(const ulonglong2*)(WtIH + k * D + u0);
        ulonglong2 whB = *(const ulonglong2*)(WtIH + k * D + u0 + 4);
        ulonglong2 wcA = *(const ulonglong2*)(WtIC + k * D + u0);
        ulonglong2 wcB = *(const ulonglong2*)(WtIC + k * D + u0 + 4);
        ah[0] = ffma2(whA.x, hh, ah[0]); ah[1] = ffma2(whA.y, hh, ah[1]);
        ah[2] = ffma2(whB.x, hh, ah[2]); ah[3] = ffma2(whB.y, hh, ah[3]);
        ac4[0] = ffma2(wcA.x, hh, ac4[0]); ac4[1] = ffma2(wcA.y, hh, ac4[1]);
        ac4[2] = ffma2(wcB.x, hh, ac4[2]); ac4[3] = ffma2(wcB.y, hh, ac4[3]);
    }
    float hn[8], c[8], wout8[8];
    #pragma unroll
    for (int pp = 0; pp < 4; pp++) {
        float a0, a1;
        unpack2(ah[pp], a0, a1);
        hn[2 * pp] = ftanhf(a0); hn[2 * pp + 1] = ftanhf(a1);
        unpack2(ac4[pp], a0, a1);
        c[2 * pp] = ftanhf(a0); c[2 * pp + 1] = ftanhf(a1);
    }
    #pragma unroll
    for (int j = 0; j < 8; j++) wout8[j] = out_w[n * D + u0 + j];
    const float ob = out_b[n];

    __syncthreads();
    #pragma unroll
    for (int j = 0; j < 8; j++)
        *(u64*)&sm->h2[u0 + j][2 * r] = pack2(hn[j], hn[j]);
    __syncthreads();

    for (int l = 0; l < LSEQ; l++) {
        u64 acc[4][4];
        #pragma unroll
        for (int t4 = 0; t4 < 4; t4++) {
            int g0 = t4 * 128 + u0;
            ulonglong2 b0 = *(const ulonglong2*)&sm->sbias[g0];
            ulonglong2 b1 = *(const ulonglong2*)&sm->sbias[g0 + 4];
            acc[t4][0] = b0.x; acc[t4][1] = b0.y;
            acc[t4][2] = b1.x; acc[t4][3] = b1.y;
        }

        #pragma unroll
        for (int kt = 0; kt < NT; kt++) {
            asm volatile("cp.async.wait_group 1;");
            __syncthreads();
            const float* wb = sm->wbuf[kt & 1];
            #pragma unroll 4
            for (int kk = 0; kk < KT; kk++) {
                int k = kt * KT + kk;
                u64 hh = *(const u64*)&sm->h2[k][2 * r];
                const float* wrow = wb + kk * GATES + u0;
                #pragma unroll
                for (int t4 = 0; t4 < 4; t4++) {
                    ulonglong2 wA = *(const ulonglong2*)(wrow + t4 * 128);
                    ulonglong2 wB = *(const ulonglong2*)(wrow + t4 * 128 + 4);
                    acc[t4][0] = ffma2(wA.x, hh, acc[t4][0]);
                    acc[t4][1] = ffma2(wA.y, hh, acc[t4][1]);
                    acc[t4][2] = ffma2(wB.x, hh, acc[t4][2]);
                    acc[t4][3] = ffma2(wB.y, hh, acc[t4][3]);
                }
            }
            __syncthreads();
            issue_tile(Wt + ((kt + 2) & 3) * TILE_F, sm->wbuf[kt & 1], tid);
        }

        #pragma unroll
        for (int pp = 0; pp < 4; pp++) {
            float i0, i1, f0, f1, g0, g1, o0, o1;
            unpack2(acc[0][pp], i0, i1);
            unpack2(acc[1][pp], f0, f1);
            unpack2(acc[2][pp], g0, g1);
            unpack2(acc[3][pp], o0, o1);
            int j = 2 * pp;
            c[j]      = fsig(f0) * c[j]     + fsig(i0) * ftanhf(g0);
            hn[j]     = fsig(o0) * ftanhf(c[j]);
            c[j + 1]  = fsig(f1) * c[j + 1] + fsig(i1) * ftanhf(g1);
            hn[j + 1] = fsig(o1) * ftanhf(c[j + 1]);
        }

        float part = 0.f;
        #pragma unroll
        for (int j = 0; j < 8; j++) part += hn[j] * wout8[j];
        part += __shfl_xor_sync(0xffffffffu, part, 16);
        #pragma unroll
        for (int j = 0; j < 8; j++)
            *(u64*)&sm->h2[u0 + j][2 * r] = pack2(hn[j], hn[j]);
        if (gh == 0) sm->sp[w][r] = part;
        __syncthreads();
        if (w == 0 && gh == 0) {
            float O = ob;
            #pragma unroll
            for (int ww = 0; ww < 8; ww++) O += sm->sp[ww][r];
            if (l < LSEQ - 1) out[(b_row * (LSEQ - 1) + l) * NVAR + n] = O;
            else              out[PRED_OFF + b_row * NVAR + n] = O;
        }
    }
    asm volatile("cp.async.wait_group 0;");
}

// ---------------- launch ----------------
extern "C" void kernel_launch(void* const* d_in, const int* in_sizes, int n_in,
                              void* d_out, int out_size) {
    (void)in_sizes; (void)n_in; (void)out_size;
    const float* X        = (const float*)d_in[0];
    const float* enc_Wih  = (const float*)d_in[1];
    const float* enc_Whh  = (const float*)d_in[2];
    const float* enc_bih  = (const float*)d_in[3];
    const float* enc_bhh  = (const float*)d_in[4];
    const float* pool_w   = (const float*)d_in[5];
    const float* pool_b   = (const float*)d_in[6];
    const float* Wqkv     = (const float*)d_in[7];
    const float* bqkv     = (const float*)d_in[8];
    const float* Wo       = (const float*)d_in[9];
    const float* bo       = (const float*)d_in[10];
    const float* dec_ih_W = (const float*)d_in[11];
    const float* dec_ih_b = (const float*)d_in[12];
    const float* dec_ic_W = (const float*)d_in[13];
    const float* dec_ic_b = (const float*)d_in[14];
    const float* dec_Whh  = (const float*)d_in[16];
    const float* dec_bih  = (const float*)d_in[17];
    const float* dec_bhh  = (const float*)d_in[18];
    const float* dec_out_W= (const float*)d_in[19];
    const float* dec_out_b= (const float*)d_in[20];
    float* out = (float*)d_out;

    static int attr_set = 0;
    if (!attr_set) {
        cudaFuncSetAttribute(mhsa_kernel, cudaFuncAttributeMaxDynamicSharedMemorySize, 66688);
        cudaFuncSetAttribute(enc_kernel,  cudaFuncAttributeMaxDynamicSharedMemorySize, SMEM_BYTES);
        cudaFuncSetAttribute(dec_kernel,  cudaFuncAttributeMaxDynamicSharedMemorySize, SMEM_BYTES);
        attr_set = 1;
    }

    float *pWtEnc, *pWtDec, *pWtIH, *pWtIC, *pWqkvT;
    cudaGetSymbolAddress((void**)&pWtEnc, g_WtEnc);
    cudaGetSymbolAddress((void**)&pWtDec, g_WtDec);
    cudaGetSymbolAddress((void**)&pWtIH,  g_WtIH);
    cudaGetSymbolAddress((void**)&pWtIC,  g_WtIC);
    cudaGetSymbolAddress((void**)&pWqkvT, g_WqkvT);

    dim3 tb(32, 8);
    transpose_kernel<<<dim3(4, 16, 32), tb>>>(enc_Whh,  pWtEnc, 512, 128);
    transpose_kernel<<<dim3(4, 16, 32), tb>>>(dec_Whh,  pWtDec, 512, 128);
    transpose_kernel<<<dim3(4,  4, 32), tb>>>(dec_ih_W, pWtIH,  128, 128);
    transpose_kernel<<<dim3(4,  4, 32), tb>>>(dec_ic_W, pWtIC,  128, 128);
    transpose_kernel<<<dim3(4, 12,  1), tb>>>(Wqkv,     pWqkvT, 384, 128);

    enc_kernel<<<dim3(PSPLIT, NVAR), 256, SMEM_BYTES>>>(X, enc_Wih, enc_bih, enc_bhh,
                                                        pool_w, pool_b);
    mhsa_kernel<<<BATCH, 128, 66688>>>(bqkv, Wo, bo, out);
    dec_kernel<<<dim3(PSPLIT, NVAR), 256, SMEM_BYTES>>>(dec_ih_b, dec_ic_b, dec_bih, dec_bhh,
                                                        dec_out_W, dec_out_b, out);
}

// round 9
// speedup vs baseline: 1.7244x; 1.0586x over previous
#include <cuda_runtime.h>
#include <cuda_bf16.h>

#define D      128
#define GATES  512
#define BATCH  64
#define NVAR   32
#define LSEQ   128
#define BSUB   16
#define PSPLIT 4
#define KT     32                      // k-rows per weight tile
#define NT     (D / KT)                // 4 tiles per step
#define TILE_F (KT * GATES)            // 16384 floats = 64KB
#define TILE_B (TILE_F * 4)            // 65536 bytes

#define RECON_SZ   260096
#define PRED_OFF   260096
#define CSTAR_OFF  262144

typedef unsigned long long u64;

// ---------------- device scratch ----------------
__device__ __align__(16) float g_WtEnc[NVAR * D * GATES];   // [n][k][g]
__device__ __align__(16) float g_WtDec[NVAR * D * GATES];   // [n][k][g]
__device__ __align__(16) float g_WtIH [NVAR * D * D];       // [n][k][e]
__device__ __align__(16) float g_WtIC [NVAR * D * D];       // [n][k][e]
__device__ __align__(16) float g_WqkvT[D * 384];            // [k][j]
__device__ __align__(16) float g_C    [BATCH * NVAR * D];   // (B,N,D)
__device__ __align__(16) float g_Cstar[BATCH * NVAR * D];   // (B,N,D)

// ---------------- helpers ----------------
__device__ __forceinline__ u64 ffma2(u64 a, u64 b, u64 c) {
    u64 d; asm("fma.rn.f32x2 %0, %1, %2, %3;" : "=l"(d) : "l"(a), "l"(b), "l"(c)); return d;
}
__device__ __forceinline__ u64 pack2(float lo, float hi) {
    u64 r; asm("mov.b64 %0, {%1, %2};" : "=l"(r) : "f"(lo), "f"(hi)); return r;
}
__device__ __forceinline__ void unpack2(u64 v, float& lo, float& hi) {
    asm("mov.b64 {%0, %1}, %2;" : "=f"(lo), "=f"(hi) : "l"(v));
}
__device__ __forceinline__ float fsig(float x)  { return __fdividef(1.f, 1.f + __expf(-x)); }
__device__ __forceinline__ float ftanhf(float x){ return 1.f - __fdividef(2.f, __expf(2.f * x) + 1.f); }

__device__ __forceinline__ unsigned smem_u32(const void* p) {
    return (unsigned)__cvta_generic_to_shared(p);
}

__device__ __forceinline__ void mbar_init(unsigned mbar, unsigned count) {
    asm volatile("mbarrier.init.shared.b64 [%0], %1;" :: "r"(mbar), "r"(count) : "memory");
}
__device__ __forceinline__ void mbar_expect_tx(unsigned mbar, unsigned bytes) {
    asm volatile("mbarrier.arrive.expect_tx.shared.b64 _, [%0], %1;"
                 :: "r"(mbar), "r"(bytes) : "memory");
}
__device__ __forceinline__ void mbar_wait(unsigned mbar, unsigned phase) {
    unsigned done;
    asm volatile(
        "{\n\t.reg .pred p;\n\t"
        "mbarrier.try_wait.parity.acquire.cta.shared::cta.b64 p, [%1], %2;\n\t"
        "selp.b32 %0, 1, 0, p;\n\t}"
        : "=r"(done) : "r"(mbar), "r"(phase) : "memory");
    if (!done) {
        asm volatile(
            "{\n\t.reg .pred P1;\n\t"
            "W_%=:\n\t"
            "mbarrier.try_wait.parity.acquire.cta.shared::cta.b64 P1, [%0], %1, 0x989680;\n\t"
            "@P1 bra.uni DN_%=;\n\t"
            "bra.uni W_%=;\n\t"
            "DN_%=:\n\t}"
            :: "r"(mbar), "r"(phase) : "memory");
    }
}
// single 64KB bulk copy, completion via mbarrier transaction bytes
__device__ __forceinline__ void bulk_tile(const float* gsrc, float* sdst, unsigned mbar) {
    asm volatile(
        "cp.async.bulk.shared::cluster.global.mbarrier::complete_tx::bytes [%0], [%1], %2, [%3];"
        :: "r"(smem_u32(sdst)), "l"(gsrc), "n"(TILE_B), "r"(mbar) : "memory");
}

struct __align__(16) SmemLSTM {
    float wbuf[2][TILE_F];   // 131072 B
    float h2[D][34];         // 17408 B  duplicated pairs h2[k][2r]==h2[k][2r+1]
    float sbias[GATES];      // 2048 B
    float swih[GATES];       // 2048 B
    float sp[8][16];         // warp partials
    float sc[16][2];
    float sinv[16];
    u64   mbar[2];
};
#define SMEM_BYTES ((int)sizeof(SmemLSTM))

// ---------------- transpose: src (batch,R,C) -> dst (batch,C,R) ----------------
__global__ void transpose_kernel(const float* __restrict__ src, float* __restrict__ dst,
                                 int R, int C) {
    __shared__ float tile[32][33];
    int n = blockIdx.z;
    src += (size_t)n * R * C;
    dst += (size_t)n * R * C;
    int c0 = blockIdx.x * 32, r0 = blockIdx.y * 32;
    #pragma unroll
    for (int i = threadIdx.y; i < 32; i += 8)
        tile[i][threadIdx.x] = src[(r0 + i) * C + c0 + threadIdx.x];
    __syncthreads();
    #pragma unroll
    for (int i = threadIdx.y; i < 32; i += 8)
        dst[(c0 + i) * R + r0 + threadIdx.x] = tile[threadIdx.x][i];
}

// ================= encoder =================
// warp w owns units [16w,16w+16); gh=lane>>4 picks 8-unit half, r=lane&15 = batch row
__global__ __launch_bounds__(256, 1) void enc_kernel(
    const float* __restrict__ X,
    const float* __restrict__ Wih,
    const float* __restrict__ bih, const float* __restrict__ bhh,
    const float* __restrict__ pool_w, const float* __restrict__ pool_b) {
    extern __shared__ __align__(16) char smraw[];
    SmemLSTM* sm = (SmemLSTM*)smraw;
    const int n = blockIdx.y, p = blockIdx.x;
    const int tid = threadIdx.x, lane = tid & 31, w = tid >> 5;
    const int gh = lane >> 4, r = lane & 15;
    const int u0 = 16 * w + 8 * gh;
    const int b_row = p * BSUB + r;

    for (int i = tid; i < GATES; i += 256) {
        sm->sbias[i] = bih[n * GATES + i] + bhh[n * GATES + i];
        sm->swih[i]  = Wih[n * GATES + i];
    }
    for (int i = tid; i < D * 34; i += 256) ((float*)sm->h2)[i] = 0.f;
    unsigned mb0 = smem_u32(&sm->mbar[0]), mb1 = smem_u32(&sm->mbar[1]);
    if (tid == 0) { mbar_init(mb0, 1); mbar_init(mb1, 1); }
    __syncthreads();

    const float* Wt = g_WtEnc + (size_t)n * D * GATES;
    if (tid == 0) {
        mbar_expect_tx(mb0, TILE_B); bulk_tile(Wt + 0 * TILE_F, sm->wbuf[0], mb0);
        mbar_expect_tx(mb1, TILE_B); bulk_tile(Wt + 1 * TILE_F, sm->wbuf[1], mb1);
    }

    float c[8], accC[8], hn[8], pw8[8];
    #pragma unroll
    for (int j = 0; j < 8; j++) {
        c[j] = 0.f; accC[j] = 0.f;
        pw8[j] = pool_w[n * D + u0 + j];
    }
    const float pb = pool_b[n];
    float pm = -1e30f, pss = 0.f;
    unsigned ph0 = 0, ph1 = 0;

    float xcur = X[(b_row * LSEQ + 0) * NVAR + n];

    for (int t = 0; t < LSEQ - 1; t++) {
        u64 acc[4][4];
        u64 xx = pack2(xcur, xcur);
        #pragma unroll
        for (int t4 = 0; t4 < 4; t4++) {
            int g0 = t4 * 128 + u0;
            ulonglong2 b0 = *(const ulonglong2*)&sm->sbias[g0];
            ulonglong2 b1 = *(const ulonglong2*)&sm->sbias[g0 + 4];
            ulonglong2 w0 = *(const ulonglong2*)&sm->swih[g0];
            ulonglong2 w1 = *(const ulonglong2*)&sm->swih[g0 + 4];
            acc[t4][0] = ffma2(w0.x, xx, b0.x);
            acc[t4][1] = ffma2(w0.y, xx, b0.y);
            acc[t4][2] = ffma2(w1.x, xx, b1.x);
            acc[t4][3] = ffma2(w1.y, xx, b1.y);
        }
        float xnext = X[(b_row * LSEQ + t + 1) * NVAR + n];

        #pragma unroll
        for (int kt = 0; kt < NT; kt++) {
            unsigned mb = (kt & 1) ? mb1 : mb0;
            if (kt & 1) { mbar_wait(mb, ph1); ph1 ^= 1; }
            else        { mbar_wait(mb, ph0); ph0 ^= 1; }
            const float* wb = sm->wbuf[kt & 1];
            #pragma unroll 4
            for (int kk = 0; kk < KT; kk++) {
                int k = kt * KT + kk;
                u64 hh = *(const u64*)&sm->h2[k][2 * r];
                const float* wrow = wb + kk * GATES + u0;
                #pragma unroll
                for (int t4 = 0; t4 < 4; t4++) {
                    ulonglong2 wA = *(const ulonglong2*)(wrow + t4 * 128);
                    ulonglong2 wB = *(const ulonglong2*)(wrow + t4 * 128 + 4);
                    acc[t4][0] = ffma2(wA.x, hh, acc[t4][0]);
                    acc[t4][1] = ffma2(wA.y, hh, acc[t4][1]);
                    acc[t4][2] = ffma2(wB.x, hh, acc[t4][2]);
                    acc[t4][3] = ffma2(wB.y, hh, acc[t4][3]);
                }
            }
            __syncthreads();   // all warps done with this buffer (and, at kt=3, with h2)
            if (tid == 0 && !(t == LSEQ - 2 && kt >= 2)) {
                mbar_expect_tx(mb, TILE_B);
                bulk_tile(Wt + ((kt + 2) & 3) * TILE_F, sm->wbuf[kt & 1], mb);
            }
        }

        #pragma unroll
        for (int pp = 0; pp < 4; pp++) {
            float i0, i1, f0, f1, g0, g1, o0, o1;
            unpack2(acc[0][pp], i0, i1);
            unpack2(acc[1][pp], f0, f1);
            unpack2(acc[2][pp], g0, g1);
            unpack2(acc[3][pp], o0, o1);
            int j = 2 * pp;
            c[j]     = fsig(f0) * c[j]     + fsig(i0) * ftanhf(g0);
            hn[j]    = fsig(o0) * ftanhf(c[j]);
            c[j + 1] = fsig(f1) * c[j + 1] + fsig(i1) * ftanhf(g1);
            hn[j + 1]= fsig(o1) * ftanhf(c[j + 1]);
        }

        float part = 0.f;
        #pragma unroll
        for (int j = 0; j < 8; j++) part += hn[j] * pw8[j];
        part += __shfl_xor_sync(0xffffffffu, part, 16);
        #pragma unroll
        for (int j = 0; j < 8; j++)
            *(u64*)&sm->h2[u0 + j][2 * r] = pack2(hn[j], hn[j]);
        if (gh == 0) sm->sp[w][r] = part;
        __syncthreads();
        if (w == 0 && gh == 0) {
            float s = pb;
            #pragma unroll
            for (int ww = 0; ww < 8; ww++) s += sm->sp[ww][r];
            float mn = fmaxf(pm, s);
            float scale = __expf(pm - mn);
            float wcur  = __expf(s - mn);
            pss = pss * scale + wcur;
            pm = mn;
            sm->sc[r][0] = scale; sm->sc[r][1] = wcur;
        }
        __syncthreads();
        float s0 = sm->sc[r][0], w0v = sm->sc[r][1];
        #pragma unroll
        for (int j = 0; j < 8; j++) accC[j] = accC[j] * s0 + w0v * hn[j];
        xcur = xnext;
    }
    if (w == 0 && gh == 0) sm->sinv[r] = __fdividef(1.f, pss);
    __syncthreads();
    float iv = sm->sinv[r];
    #pragma unroll
    for (int j = 0; j < 8; j++)
        g_C[(b_row * NVAR + n) * D + u0 + j] = accC[j] * iv;
}

// ================= MHSA =================
__global__ __launch_bounds__(128, 1) void mhsa_kernel(
    const float* __restrict__ bqkv,
    const float* __restrict__ Wo, const float* __restrict__ bo,
    float* __restrict__ out) {
    extern __shared__ __align__(16) float smf[];
    float* Cs  = smf;            // [128][34]
    float* QKV = smf + 4352;     // [32][385]
    float* As  = smf;            // [32][129] reuse
    const int b = blockIdx.x, tid = threadIdx.x;

    #pragma unroll 4
    for (int i = 0; i < 32; i++)
        Cs[tid * 34 + i] = g_C[(b * NVAR + i) * D + tid];
    __syncthreads();

    for (int jj = 0; jj < 3; jj++) {
        int j = jj * 128 + tid;
        float bj = bqkv[j];
        u64 acc[16];
        #pragma unroll
        for (int vp = 0; vp < 16; vp++) acc[vp] = pack2(bj, bj);
        #pragma unroll 2
        for (int k = 0; k < D; k++) {
            float wv = g_WqkvT[k * 384 + j];
            u64 ww = pack2(wv, wv);
            const u64* crow = (const u64*)&Cs[k * 34];
            #pragma unroll
            for (int vp = 0; vp < 16; vp++) acc[vp] = ffma2(ww, crow[vp], acc[vp]);
        }
        #pragma unroll
        for (int vp = 0; vp < 16; vp++) {
            float a0, a1; unpack2(acc[vp], a0, a1);
            QKV[(2 * vp)     * 385 + j] = a0;
            QKV[(2 * vp + 1) * 385 + j] = a1;
        }
    }
    __syncthreads();

    {
        int h = tid >> 5, i = tid & 31;
        float q[32];
        #pragma unroll
        for (int d = 0; d < 32; d++) q[d] = QKV[i * 385 + h * 32 + d];
        float s[32];
        #pragma unroll
        for (int j = 0; j < 32; j++) {
            float a = 0.f;
            #pragma unroll
            for (int d = 0; d < 32; d++) a += q[d] * QKV[j * 385 + 128 + h * 32 + d];
            s[j] = a * 0.17677669529663687f;
        }
        float mx = s[0];
        #pragma unroll
        for (int j = 1; j < 32; j++) mx = fmaxf(mx, s[j]);
        float sum = 0.f;
        #pragma unroll
        for (int j = 0; j < 32; j++) { s[j] = __expf(s[j] - mx); sum += s[j]; }
        float inv = __fdividef(1.f, sum);
        float A[32];
        #pragma unroll
        for (int d = 0; d < 32; d++) A[d] = 0.f;
        #pragma unroll
        for (int j = 0; j < 32; j++) {
            float aj = s[j] * inv;
            #pragma unroll
            for (int d = 0; d < 32; d++) A[d] += aj * QKV[j * 385 + 256 + h * 32 + d];
        }
        #pragma unroll
        for (int d = 0; d < 32; d++) As[i * 129 + h * 32 + d] = A[d];
    }
    __syncthreads();

    {
        int v = tid & 31, uc = tid >> 5;
        for (int mm = 0; mm < 32; mm++) {
            int u = uc * 32 + mm;
            float a = bo[u];
            #pragma unroll 4
            for (int d = 0; d < D; d++) a += As[v * 129 + d] * Wo[u * D + d];
            g_Cstar[(b * NVAR + v) * D + u] = a;
            out[CSTAR_OFF + (b * NVAR + v) * D + u] = a;
        }
    }
}

// ================= decoder =================
__global__ __launch_bounds__(256, 1) void dec_kernel(
    const float* __restrict__ ih_b, const float* __restrict__ ic_b,
    const float* __restrict__ bih,  const float* __restrict__ bhh,
    const float* __restrict__ out_w, const float* __restrict__ out_b,
    float* __restrict__ out) {
    extern __shared__ __align__(16) char smraw[];
    SmemLSTM* sm = (SmemLSTM*)smraw;
    const int n = blockIdx.y, p = blockIdx.x;
    const int tid = threadIdx.x, lane = tid & 31, w = tid >> 5;
    const int gh = lane >> 4, r = lane & 15;
    const int u0 = 16 * w + 8 * gh;
    const int b_row = p * BSUB + r;

    for (int i = tid; i < GATES; i += 256)
        sm->sbias[i] = bih[n * GATES + i] + bhh[n * GATES + i];
    #pragma unroll
    for (int i = 0; i < 8; i++) {
        int idx = i * 256 + tid;
        int rr = idx >> 7, k = idx & 127;
        float v = g_Cstar[((p * BSUB + rr) * NVAR + n) * D + k];
        sm->h2[k][2 * rr] = v; sm->h2[k][2 * rr + 1] = v;
    }
    unsigned mb0 = smem_u32(&sm->mbar[0]), mb1 = smem_u32(&sm->mbar[1]);
    if (tid == 0) { mbar_init(mb0, 1); mbar_init(mb1, 1); }
    __syncthreads();

    const float* Wt = g_WtDec + (size_t)n * D * GATES;
    if (tid == 0) {
        mbar_expect_tx(mb0, TILE_B); bulk_tile(Wt + 0 * TILE_F, sm->wbuf[0], mb0);
        mbar_expect_tx(mb1, TILE_B); bulk_tile(Wt + 1 * TILE_F, sm->wbuf[1], mb1);
    }

    // init matvecs (overlap with bulk loads)
    const float* WtIH = g_WtIH + (size_t)n * D * D;
    const float* WtIC = g_WtIC + (size_t)n * D * D;
    u64 ah[4], ac4[4];
    #pragma unroll
    for (int pp = 0; pp < 4; pp++) {
        int e = u0 + 2 * pp;
        ah[pp]  = pack2(ih_b[n * D + e], ih_b[n * D + e + 1]);
        ac4[pp] = pack2(ic_b[n * D + e], ic_b[n * D + e + 1]);
    }
    #pragma unroll 2
    for (int k = 0; k < D; k++) {
        u64 hh = *(const u64*)&sm->h2[k][2 * r];
        ulonglong2 whA = *(const ulonglong2*)(WtIH + k * D + u0);
        ulonglong2 whB = *(const ulonglong2*)(WtIH + k * D + u0 + 4);
        ulonglong2 wcA = *(const ulonglong2*)(WtIC + k * D + u0);
        ulonglong2 wcB = *(const ulonglong2*)(WtIC + k * D + u0 + 4);
        ah[0] = ffma2(whA.x, hh, ah[0]); ah[1] = ffma2(whA.y, hh, ah[1]);
        ah[2] = ffma2(whB.x, hh, ah[2]); ah[3] = ffma2(whB.y, hh, ah[3]);
        ac4[0] = ffma2(wcA.x, hh, ac4[0]); ac4[1] = ffma2(wcA.y, hh, ac4[1]);
        ac4[2] = ffma2(wcB.x, hh, ac4[2]); ac4[3] = ffma2(wcB.y, hh, ac4[3]);
    }
    float hn[8], c[8], wout8[8];
    #pragma unroll
    for (int pp = 0; pp < 4; pp++) {
        float a0, a1;
        unpack2(ah[pp], a0, a1);
        hn[2 * pp] = ftanhf(a0); hn[2 * pp + 1] = ftanhf(a1);
        unpack2(ac4[pp], a0, a1);
        c[2 * pp] = ftanhf(a0); c[2 * pp + 1] = ftanhf(a1);
    }
    #pragma unroll
    for (int j = 0; j < 8; j++) wout8[j] = out_w[n * D + u0 + j];
    const float ob = out_b[n];

    __syncthreads();
    #pragma unroll
    for (int j = 0; j < 8; j++)
        *(u64*)&sm->h2[u0 + j][2 * r] = pack2(hn[j], hn[j]);
    __syncthreads();

    unsigned ph0 = 0, ph1 = 0;

    for (int l = 0; l < LSEQ; l++) {
        u64 acc[4][4];
        #pragma unroll
        for (int t4 = 0; t4 < 4; t4++) {
            int g0 = t4 * 128 + u0;
            ulonglong2 b0 = *(const ulonglong2*)&sm->sbias[g0];
            ulonglong2 b1 = *(const ulonglong2*)&sm->sbias[g0 + 4];
            acc[t4][0] = b0.x; acc[t4][1] = b0.y;
            acc[t4][2] = b1.x; acc[t4][3] = b1.y;
        }

        #pragma unroll
        for (int kt = 0; kt < NT; kt++) {
            unsigned mb = (kt & 1) ? mb1 : mb0;
            if (kt & 1) { mbar_wait(mb, ph1); ph1 ^= 1; }
            else        { mbar_wait(mb, ph0); ph0 ^= 1; }
            const float* wb = sm->wbuf[kt & 1];
            #pragma unroll 4
            for (int kk = 0; kk < KT; kk++) {
                int k = kt * KT + kk;
                u64 hh = *(const u64*)&sm->h2[k][2 * r];
                const float* wrow = wb + kk * GATES + u0;
                #pragma unroll
                for (int t4 = 0; t4 < 4; t4++) {
                    ulonglong2 wA = *(const ulonglong2*)(wrow + t4 * 128);
                    ulonglong2 wB = *(const ulonglong2*)(wrow + t4 * 128 + 4);
                    acc[t4][0] = ffma2(wA.x, hh, acc[t4][0]);
                    acc[t4][1] = ffma2(wA.y, hh, acc[t4][1]);
                    acc[t4][2] = ffma2(wB.x, hh, acc[t4][2]);
                    acc[t4][3] = ffma2(wB.y, hh, acc[t4][3]);
                }
            }
            __syncthreads();
            if (tid == 0 && !(l == LSEQ - 1 && kt >= 2)) {
                mbar_expect_tx(mb, TILE_B);
                bulk_tile(Wt + ((kt + 2) & 3) * TILE_F, sm->wbuf[kt & 1], mb);
            }
        }

        #pragma unroll
        for (int pp = 0; pp < 4; pp++) {
            float i0, i1, f0, f1, g0, g1, o0, o1;
            unpack2(acc[0][pp], i0, i1);
            unpack2(acc[1][pp], f0, f1);
            unpack2(acc[2][pp], g0, g1);
            unpack2(acc[3][pp], o0, o1);
            int j = 2 * pp;
            c[j]      = fsig(f0) * c[j]     + fsig(i0) * ftanhf(g0);
            hn[j]     = fsig(o0) * ftanhf(c[j]);
            c[j + 1]  = fsig(f1) * c[j + 1] + fsig(i1) * ftanhf(g1);
            hn[j + 1] = fsig(o1) * ftanhf(c[j + 1]);
        }

        float part = 0.f;
        #pragma unroll
        for (int j = 0; j < 8; j++) part += hn[j] * wout8[j];
        part += __shfl_xor_sync(0xffffffffu, part, 16);
        #pragma unroll
        for (int j = 0; j < 8; j++)
            *(u64*)&sm->h2[u0 + j][2 * r] = pack2(hn[j], hn[j]);
        if (gh == 0) sm->sp[w][r] = part;
        __syncthreads();
        if (w == 0 && gh == 0) {
            float O = ob;
            #pragma unroll
            for (int ww = 0; ww < 8; ww++) O += sm->sp[ww][r];
            if (l < LSEQ - 1) out[(b_row * (LSEQ - 1) + l) * NVAR + n] = O;
            else              out[PRED_OFF + b_row * NVAR + n] = O;
        }
    }
}

// ---------------- launch ----------------
extern "C" void kernel_launch(void* const* d_in, const int* in_sizes, int n_in,
                              void* d_out, int out_size) {
    (void)in_sizes; (void)n_in; (void)out_size;
    const float* X        = (const float*)d_in[0];
    const float* enc_Wih  = (const float*)d_in[1];
    const float* enc_Whh  = (const float*)d_in[2];
    const float* enc_bih  = (const float*)d_in[3];
    const float* enc_bhh  = (const float*)d_in[4];
    const float* pool_w   = (const float*)d_in[5];
    const float* pool_b   = (const float*)d_in[6];
    const float* Wqkv     = (const float*)d_in[7];
    const float* bqkv     = (const float*)d_in[8];
    const float* Wo       = (const float*)d_in[9];
    const float* bo       = (const float*)d_in[10];
    const float* dec_ih_W = (const float*)d_in[11];
    const float* dec_ih_b = (const float*)d_in[12];
    const float* dec_ic_W = (const float*)d_in[13];
    const float* dec_ic_b = (const float*)d_in[14];
    const float* dec_Whh  = (const float*)d_in[16];
    const float* dec_bih  = (const float*)d_in[17];
    const float* dec_bhh  = (const float*)d_in[18];
    const float* dec_out_W= (const float*)d_in[19];
    const float* dec_out_b= (const float*)d_in[20];
    float* out = (float*)d_out;

    static int attr_set = 0;
    if (!attr_set) {
        cudaFuncSetAttribute(mhsa_kernel, cudaFuncAttributeMaxDynamicSharedMemorySize, 66688);
        cudaFuncSetAttribute(enc_kernel,  cudaFuncAttributeMaxDynamicSharedMemorySize, SMEM_BYTES);
        cudaFuncSetAttribute(dec_kernel,  cudaFuncAttributeMaxDynamicSharedMemorySize, SMEM_BYTES);
        attr_set = 1;
    }

    float *pWtEnc, *pWtDec, *pWtIH, *pWtIC, *pWqkvT;
    cudaGetSymbolAddress((void**)&pWtEnc, g_WtEnc);
    cudaGetSymbolAddress((void**)&pWtDec, g_WtDec);
    cudaGetSymbolAddress((void**)&pWtIH,  g_WtIH);
    cudaGetSymbolAddress((void**)&pWtIC,  g_WtIC);
    cudaGetSymbolAddress((void**)&pWqkvT, g_WqkvT);

    dim3 tb(32, 8);
    transpose_kernel<<<dim3(4, 16, 32), tb>>>(enc_Whh,  pWtEnc, 512, 128);
    transpose_kernel<<<dim3(4, 16, 32), tb>>>(dec_Whh,  pWtDec, 512, 128);
    transpose_kernel<<<dim3(4,  4, 32), tb>>>(dec_ih_W, pWtIH,  128, 128);
    transpose_kernel<<<dim3(4,  4, 32), tb>>>(dec_ic_W, pWtIC,  128, 128);
    transpose_kernel<<<dim3(4, 12,  1), tb>>>(Wqkv,     pWqkvT, 384, 128);

    enc_kernel<<<dim3(PSPLIT, NVAR), 256, SMEM_BYTES>>>(X, enc_Wih, enc_bih, enc_bhh,
                                                        pool_w, pool_b);
    mhsa_kernel<<<BATCH, 128, 66688>>>(bqkv, Wo, bo, out);
    dec_kernel<<<dim3(PSPLIT, NVAR), 256, SMEM_BYTES>>>(dec_ih_b, dec_ic_b, dec_bih, dec_bhh,
                                                        dec_out_W, dec_out_b, out);
}

// round 10
// speedup vs baseline: 1.7391x; 1.0085x over previous
#include <cuda_runtime.h>
#include <cuda_bf16.h>

#define D      128
#define GATES  512
#define BATCH  64
#define NVAR   32
#define LSEQ   128
#define BSUB   16
#define PSPLIT 4

#define RES_K   64                       // resident k rows (k 0..63)
#define RES_F   (RES_K * GATES)          // 32768 floats = 128KB
#define RES_B   (RES_F * 4)
#define CHUNK_K 16                       // streamed chunk k rows
#define CHUNK_F (CHUNK_K * GATES)        // 8192 floats = 32KB
#define CHUNK_B (CHUNK_F * 4)

#define RECON_SZ   260096
#define PRED_OFF   260096
#define CSTAR_OFF  262144

typedef unsigned long long u64;

// ---------------- device scratch ----------------
__device__ __align__(16) float g_WtEnc[NVAR * D * GATES];   // [n][k][g]
__device__ __align__(16) float g_WtDec[NVAR * D * GATES];   // [n][k][g]
__device__ __align__(16) float g_WtIH [NVAR * D * D];       // [n][k][e]
__device__ __align__(16) float g_WtIC [NVAR * D * D];       // [n][k][e]
__device__ __align__(16) float g_WqkvT[D * 384];            // [k][j]
__device__ __align__(16) float g_C    [BATCH * NVAR * D];   // (B,N,D)
__device__ __align__(16) float g_Cstar[BATCH * NVAR * D];   // (B,N,D)

// ---------------- helpers ----------------
__device__ __forceinline__ u64 ffma2(u64 a, u64 b, u64 c) {
    u64 d; asm("fma.rn.f32x2 %0, %1, %2, %3;" : "=l"(d) : "l"(a), "l"(b), "l"(c)); return d;
}
__device__ __forceinline__ u64 pack2(float lo, float hi) {
    u64 r; asm("mov.b64 %0, {%1, %2};" : "=l"(r) : "f"(lo), "f"(hi)); return r;
}
__device__ __forceinline__ void unpack2(u64 v, float& lo, float& hi) {
    asm("mov.b64 {%0, %1}, %2;" : "=f"(lo), "=f"(hi) : "l"(v));
}
__device__ __forceinline__ float fsig(float x)  { return __fdividef(1.f, 1.f + __expf(-x)); }
__device__ __forceinline__ float ftanhf(float x){ return 1.f - __fdividef(2.f, __expf(2.f * x) + 1.f); }

__device__ __forceinline__ unsigned smem_u32(const void* p) {
    return (unsigned)__cvta_generic_to_shared(p);
}
__device__ __forceinline__ void mbar_init(unsigned mbar, unsigned count) {
    asm volatile("mbarrier.init.shared.b64 [%0], %1;" :: "r"(mbar), "r"(count) : "memory");
}
__device__ __forceinline__ void mbar_expect_tx(unsigned mbar, unsigned bytes) {
    asm volatile("mbarrier.arrive.expect_tx.shared.b64 _, [%0], %1;"
                 :: "r"(mbar), "r"(bytes) : "memory");
}
__device__ __forceinline__ void mbar_wait(unsigned mbar, unsigned phase) {
    unsigned done;
    asm volatile(
        "{\n\t.reg .pred p;\n\t"
        "mbarrier.try_wait.parity.acquire.cta.shared::cta.b64 p, [%1], %2;\n\t"
        "selp.b32 %0, 1, 0, p;\n\t}"
        : "=r"(done) : "r"(mbar), "r"(phase) : "memory");
    if (!done) {
        asm volatile(
            "{\n\t.reg .pred P1;\n\t"
            "W_%=:\n\t"
            "mbarrier.try_wait.parity.acquire.cta.shared::cta.b64 P1, [%0], %1, 0x989680;\n\t"
            "@P1 bra.uni DN_%=;\n\t"
            "bra.uni W_%=;\n\t"
            "DN_%=:\n\t}"
            :: "r"(mbar), "r"(phase) : "memory");
    }
}
__device__ __forceinline__ void bulk_copy(const float* gsrc, float* sdst,
                                          unsigned bytes, unsigned mbar) {
    asm volatile(
        "cp.async.bulk.shared::cluster.global.mbarrier::complete_tx::bytes [%0], [%1], %2, [%3];"
        :: "r"(smem_u32(sdst)), "l"(gsrc), "r"(bytes), "r"(mbar) : "memory");
}

struct __align__(16) SmemLSTM {
    float rbuf[RES_F];       // 131072 B resident weights k0..63
    float sbuf[2][CHUNK_F];  // 65536 B  streamed chunks
    float h2[D][34];         // 17408 B  duplicated pairs
    float sbias[GATES];      // 2048
    float swih[GATES];       // 2048
    float sp[8][16];         // 512
    u64   mbar[4];           // R, b0, b1
};
#define SMEM_BYTES ((int)sizeof(SmemLSTM))

// one k-chunk of the gate GEMM
__device__ __forceinline__ void gemm_chunk(const float* __restrict__ wb,
                                           const float (*h2)[34], int k0, int kcount,
                                           int r, int u0, u64 acc[4][4]) {
    #pragma unroll 4
    for (int kk = 0; kk < kcount; kk++) {
        u64 hh = *(const u64*)&h2[k0 + kk][2 * r];
        const float* wrow = wb + kk * GATES + u0;
        #pragma unroll
        for (int t4 = 0; t4 < 4; t4++) {
            ulonglong2 wA = *(const ulonglong2*)(wrow + t4 * 128);
            ulonglong2 wB = *(const ulonglong2*)(wrow + t4 * 128 + 4);
            acc[t4][0] = ffma2(wA.x, hh, acc[t4][0]);
            acc[t4][1] = ffma2(wA.y, hh, acc[t4][1]);
            acc[t4][2] = ffma2(wB.x, hh, acc[t4][2]);
            acc[t4][3] = ffma2(wB.y, hh, acc[t4][3]);
        }
    }
}

// ---------------- transpose ----------------
__global__ void transpose_kernel(const float* __restrict__ src, float* __restrict__ dst,
                                 int R, int C) {
    __shared__ float tile[32][33];
    int n = blockIdx.z;
    src += (size_t)n * R * C;
    dst += (size_t)n * R * C;
    int c0 = blockIdx.x * 32, r0 = blockIdx.y * 32;
    #pragma unroll
    for (int i = threadIdx.y; i < 32; i += 8)
        tile[i][threadIdx.x] = src[(r0 + i) * C + c0 + threadIdx.x];
    __syncthreads();
    #pragma unroll
    for (int i = threadIdx.y; i < 32; i += 8)
        dst[(c0 + i) * R + r0 + threadIdx.x] = tile[threadIdx.x][i];
}

// ================= encoder =================
__global__ __launch_bounds__(256, 1) void enc_kernel(
    const float* __restrict__ X,
    const float* __restrict__ Wih,
    const float* __restrict__ bih, const float* __restrict__ bhh,
    const float* __restrict__ pool_w, const float* __restrict__ pool_b) {
    extern __shared__ __align__(16) char smraw[];
    SmemLSTM* sm = (SmemLSTM*)smraw;
    const int n = blockIdx.y, p = blockIdx.x;
    const int tid = threadIdx.x, lane = tid & 31, w = tid >> 5;
    const int gh = lane >> 4, r = lane & 15;
    const int u0 = 16 * w + 8 * gh;
    const int b_row = p * BSUB + r;

    for (int i = tid; i < GATES; i += 256) {
        sm->sbias[i] = bih[n * GATES + i] + bhh[n * GATES + i];
        sm->swih[i]  = Wih[n * GATES + i];
    }
    for (int i = tid; i < D * 34; i += 256) ((float*)sm->h2)[i] = 0.f;
    unsigned mbR = smem_u32(&sm->mbar[0]);
    unsigned mb0 = smem_u32(&sm->mbar[1]);
    unsigned mb1 = smem_u32(&sm->mbar[2]);
    if (tid == 0) { mbar_init(mbR, 1); mbar_init(mb0, 1); mbar_init(mb1, 1); }
    __syncthreads();

    const float* Wt = g_WtEnc + (size_t)n * D * GATES;
    if (tid == 0) {
        mbar_expect_tx(mbR, RES_B);
        bulk_copy(Wt,              sm->rbuf,            RES_B / 2, mbR);
        bulk_copy(Wt + RES_F / 2,  sm->rbuf + RES_F / 2, RES_B / 2, mbR);
        mbar_expect_tx(mb0, CHUNK_B);
        bulk_copy(Wt + 64 * GATES, sm->sbuf[0], CHUNK_B, mb0);   // c0: k64..79
        mbar_expect_tx(mb1, CHUNK_B);
        bulk_copy(Wt + 80 * GATES, sm->sbuf[1], CHUNK_B, mb1);   // c1: k80..95
    }

    float c[8], accC[8], hn[8], pw8[8];
    #pragma unroll
    for (int j = 0; j < 8; j++) {
        c[j] = 0.f; accC[j] = 0.f;
        pw8[j] = pool_w[n * D + u0 + j];
    }
    const float pb = pool_b[n];
    float pm = -1e30f, pss = 0.f;       // replicated per lane
    unsigned ph0 = 0, ph1 = 0;

    float xcur = X[(b_row * LSEQ + 0) * NVAR + n];

    for (int t = 0; t < LSEQ - 1; t++) {
        u64 acc[4][4];
        u64 xx = pack2(xcur, xcur);
        #pragma unroll
        for (int t4 = 0; t4 < 4; t4++) {
            int g0 = t4 * 128 + u0;
            ulonglong2 b0 = *(const ulonglong2*)&sm->sbias[g0];
            ulonglong2 b1 = *(const ulonglong2*)&sm->sbias[g0 + 4];
            ulonglong2 w0 = *(const ulonglong2*)&sm->swih[g0];
            ulonglong2 w1 = *(const ulonglong2*)&sm->swih[g0 + 4];
            acc[t4][0] = ffma2(w0.x, xx, b0.x);
            acc[t4][1] = ffma2(w0.y, xx, b0.y);
            acc[t4][2] = ffma2(w1.x, xx, b1.x);
            acc[t4][3] = ffma2(w1.y, xx, b1.y);
        }
        float xnext = X[(b_row * LSEQ + t + 1) * NVAR + n];

        if (t == 0) mbar_wait(mbR, 0);
        gemm_chunk(sm->rbuf, sm->h2, 0, 32, r, u0, acc);               // R0: k0..31

        mbar_wait(mb0, ph0); ph0 ^= 1;
        gemm_chunk(sm->sbuf[0], sm->h2, 64, CHUNK_K, r, u0, acc);      // c0
        __syncthreads();
        if (tid == 0) { mbar_expect_tx(mb0, CHUNK_B);
                        bulk_copy(Wt + 96 * GATES, sm->sbuf[0], CHUNK_B, mb0); }  // c2

        mbar_wait(mb1, ph1); ph1 ^= 1;
        gemm_chunk(sm->sbuf[1], sm->h2, 80, CHUNK_K, r, u0, acc);      // c1
        __syncthreads();
        if (tid == 0) { mbar_expect_tx(mb1, CHUNK_B);
                        bulk_copy(Wt + 112 * GATES, sm->sbuf[1], CHUNK_B, mb1); } // c3

        gemm_chunk(sm->rbuf + 32 * GATES, sm->h2, 32, 32, r, u0, acc); // R1: k32..63

        mbar_wait(mb0, ph0); ph0 ^= 1;
        gemm_chunk(sm->sbuf[0], sm->h2, 96, CHUNK_K, r, u0, acc);      // c2
        __syncthreads();
        if (tid == 0 && t < LSEQ - 2) { mbar_expect_tx(mb0, CHUNK_B);
                        bulk_copy(Wt + 64 * GATES, sm->sbuf[0], CHUNK_B, mb0); }  // next c0

        mbar_wait(mb1, ph1); ph1 ^= 1;
        gemm_chunk(sm->sbuf[1], sm->h2, 112, CHUNK_K, r, u0, acc);     // c3
        __syncthreads();   // buf1 free + all h2 reads done
        if (tid == 0 && t < LSEQ - 2) { mbar_expect_tx(mb1, CHUNK_B);
                        bulk_copy(Wt + 80 * GATES, sm->sbuf[1], CHUNK_B, mb1); }  // next c1

        // nonlinearity (overlaps DMAs)
        #pragma unroll
        for (int pp = 0; pp < 4; pp++) {
            float i0, i1, f0, f1, g0, g1, o0, o1;
            unpack2(acc[0][pp], i0, i1);
            unpack2(acc[1][pp], f0, f1);
            unpack2(acc[2][pp], g0, g1);
            unpack2(acc[3][pp], o0, o1);
            int j = 2 * pp;
            c[j]     = fsig(f0) * c[j]     + fsig(i0) * ftanhf(g0);
            hn[j]    = fsig(o0) * ftanhf(c[j]);
            c[j + 1] = fsig(f1) * c[j + 1] + fsig(i1) * ftanhf(g1);
            hn[j + 1]= fsig(o1) * ftanhf(c[j + 1]);
        }

        // pooling partial + h2 for next step
        float part = 0.f;
        #pragma unroll
        for (int j = 0; j < 8; j++) part += hn[j] * pw8[j];
        part += __shfl_xor_sync(0xffffffffu, part, 16);
        #pragma unroll
        for (int j = 0; j < 8; j++)
            *(u64*)&sm->h2[u0 + j][2 * r] = pack2(hn[j], hn[j]);
        if (gh == 0) sm->sp[w][r] = part;
        __syncthreads();

        // every lane redundantly reduces -> no second barrier
        float s = pb;
        #pragma unroll
        for (int ww = 0; ww < 8; ww++) s += sm->sp[ww][r];
        float mn = fmaxf(pm, s);
        float scale = __expf(pm - mn);
        float wcur  = __expf(s - mn);
        pss = pss * scale + wcur;
        pm = mn;
        #pragma unroll
        for (int j = 0; j < 8; j++) accC[j] = accC[j] * scale + wcur * hn[j];
        xcur = xnext;
    }
    float iv = __fdividef(1.f, pss);
    #pragma unroll
    for (int j = 0; j < 8; j++)
        g_C[(b_row * NVAR + n) * D + u0 + j] = accC[j] * iv;
}

// ================= MHSA =================
__global__ __launch_bounds__(128, 1) void mhsa_kernel(
    const float* __restrict__ bqkv,
    const float* __restrict__ Wo, const float* __restrict__ bo,
    float* __restrict__ out) {
    extern __shared__ __align__(16) float smf[];
    float* Cs  = smf;            // [128][34]
    float* QKV = smf + 4352;     // [32][385]
    float* As  = smf;            // [32][129] reuse
    const int b = blockIdx.x, tid = threadIdx.x;

    #pragma unroll 4
    for (int i = 0; i < 32; i++)
        Cs[tid * 34 + i] = g_C[(b * NVAR + i) * D + tid];
    __syncthreads();

    for (int jj = 0; jj < 3; jj++) {
        int j = jj * 128 + tid;
        float bj = bqkv[j];
        u64 acc[16];
        #pragma unroll
        for (int vp = 0; vp < 16; vp++) acc[vp] = pack2(bj, bj);
        #pragma unroll 2
        for (int k = 0; k < D; k++) {
            float wv = g_WqkvT[k * 384 + j];
            u64 ww = pack2(wv, wv);
            const u64* crow = (const u64*)&Cs[k * 34];
            #pragma unroll
            for (int vp = 0; vp < 16; vp++) acc[vp] = ffma2(ww, crow[vp], acc[vp]);
        }
        #pragma unroll
        for (int vp = 0; vp < 16; vp++) {
            float a0, a1; unpack2(acc[vp], a0, a1);
            QKV[(2 * vp)     * 385 + j] = a0;
            QKV[(2 * vp + 1) * 385 + j] = a1;
        }
    }
    __syncthreads();

    {
        int h = tid >> 5, i = tid & 31;
        float q[32];
        #pragma unroll
        for (int d = 0; d < 32; d++) q[d] = QKV[i * 385 + h * 32 + d];
        float s[32];
        #pragma unroll
        for (int j = 0; j < 32; j++) {
            float a = 0.f;
            #pragma unroll
            for (int d = 0; d < 32; d++) a += q[d] * QKV[j * 385 + 128 + h * 32 + d];
            s[j] = a * 0.17677669529663687f;
        }
        float mx = s[0];
        #pragma unroll
        for (int j = 1; j < 32; j++) mx = fmaxf(mx, s[j]);
        float sum = 0.f;
        #pragma unroll
        for (int j = 0; j < 32; j++) { s[j] = __expf(s[j] - mx); sum += s[j]; }
        float inv = __fdividef(1.f, sum);
        float A[32];
        #pragma unroll
        for (int d = 0; d < 32; d++) A[d] = 0.f;
        #pragma unroll
        for (int j = 0; j < 32; j++) {
            float aj = s[j] * inv;
            #pragma unroll
            for (int d = 0; d < 32; d++) A[d] += aj * QKV[j * 385 + 256 + h * 32 + d];
        }
        #pragma unroll
        for (int d = 0; d < 32; d++) As[i * 129 + h * 32 + d] = A[d];
    }
    __syncthreads();

    {
        int v = tid & 31, uc = tid >> 5;
        for (int mm = 0; mm < 32; mm++) {
            int u = uc * 32 + mm;
            float a = bo[u];
            #pragma unroll 4
            for (int d = 0; d < D; d++) a += As[v * 129 + d] * Wo[u * D + d];
            g_Cstar[(b * NVAR + v) * D + u] = a;
            out[CSTAR_OFF + (b * NVAR + v) * D + u] = a;
        }
    }
}

// ================= decoder =================
__global__ __launch_bounds__(256, 1) void dec_kernel(
    const float* __restrict__ ih_b, const float* __restrict__ ic_b,
    const float* __restrict__ bih,  const float* __restrict__ bhh,
    const float* __restrict__ out_w, const float* __restrict__ out_b,
    float* __restrict__ out) {
    extern __shared__ __align__(16) char smraw[];
    SmemLSTM* sm = (SmemLSTM*)smraw;
    const int n = blockIdx.y, p = blockIdx.x;
    const int tid = threadIdx.x, lane = tid & 31, w = tid >> 5;
    const int gh = lane >> 4, r = lane & 15;
    const int u0 = 16 * w + 8 * gh;
    const int b_row = p * BSUB + r;

    for (int i = tid; i < GATES; i += 256)
        sm->sbias[i] = bih[n * GATES + i] + bhh[n * GATES + i];
    #pragma unroll
    for (int i = 0; i < 8; i++) {
        int idx = i * 256 + tid;
        int rr = idx >> 7, k = idx & 127;
        float v = g_Cstar[((p * BSUB + rr) * NVAR + n) * D + k];
        sm->h2[k][2 * rr] = v; sm->h2[k][2 * rr + 1] = v;
    }
    unsigned mbR = smem_u32(&sm->mbar[0]);
    unsigned mb0 = smem_u32(&sm->mbar[1]);
    unsigned mb1 = smem_u32(&sm->mbar[2]);
    if (tid == 0) { mbar_init(mbR, 1); mbar_init(mb0, 1); mbar_init(mb1, 1); }
    __syncthreads();

    const float* Wt = g_WtDec + (size_t)n * D * GATES;
    if (tid == 0) {
        mbar_expect_tx(mbR, RES_B);
        bulk_copy(Wt,             sm->rbuf,             RES_B / 2, mbR);
        bulk_copy(Wt + RES_F / 2, sm->rbuf + RES_F / 2, RES_B / 2, mbR);
        mbar_expect_tx(mb0, CHUNK_B);
        bulk_copy(Wt + 64 * GATES, sm->sbuf[0], CHUNK_B, mb0);
        mbar_expect_tx(mb1, CHUNK_B);
        bulk_copy(Wt + 80 * GATES, sm->sbuf[1], CHUNK_B, mb1);
    }

    // init matvecs (overlap with bulk loads)
    const float* WtIH = g_WtIH + (size_t)n * D * D;
    const float* WtIC = g_WtIC + (size_t)n * D * D;
    u64 ah[4], ac4[4];
    #pragma unroll
    for (int pp = 0; pp < 4; pp++) {
        int e = u0 + 2 * pp;
        ah[pp]  = pack2(ih_b[n * D + e], ih_b[n * D + e + 1]);
        ac4[pp] = pack2(ic_b[n * D + e], ic_b[n * D + e + 1]);
    }
    #pragma unroll 2
    for (int k = 0; k < D; k++) {
        u64 hh = *(const u64*)&sm->h2[k][2 * r];
        ulonglong2 whA = *(const ulonglong2*)(WtIH + k * D + u0);
        ulonglong2 whB = *(const ulonglong2*)(WtIH + k * D + u0 + 4);
        ulonglong2 wcA = *(const ulonglong2*)(WtIC + k * D + u0);
        ulonglong2 wcB = *(const ulonglong2*)(WtIC + k * D + u0 + 4);
        ah[0] = ffma2(whA.x, hh, ah[0]); ah[1] = ffma2(whA.y, hh, ah[1]);
        ah[2] = ffma2(whB.x, hh, ah[2]); ah[3] = ffma2(whB.y, hh, ah[3]);
        ac4[0] = ffma2(wcA.x, hh, ac4[0]); ac4[1] = ffma2(wcA.y, hh, ac4[1]);
        ac4[2] = ffma2(wcB.x, hh, ac4[2]); ac4[3] = ffma2(wcB.y, hh, ac4[3]);
    }
    float hn[8], c[8], wout8[8];
    #pragma unroll
    for (int pp = 0; pp < 4; pp++) {
        float a0, a1;
        unpack2(ah[pp], a0, a1);
        hn[2 * pp] = ftanhf(a0); hn[2 * pp + 1] = ftanhf(a1);
        unpack2(ac4[pp], a0, a1);
        c[2 * pp] = ftanhf(a0); c[2 * pp + 1] = ftanhf(a1);
    }
    #pragma unroll
    for (int j = 0; j < 8; j++) wout8[j] = out_w[n * D + u0 + j];
    const float ob = out_b[n];

    __syncthreads();                 // everyone done reading staged C_star from h2
    #pragma unroll
    for (int j = 0; j < 8; j++)
        *(u64*)&sm->h2[u0 + j][2 * r] = pack2(hn[j], hn[j]);
    __syncthreads();

    unsigned ph0 = 0, ph1 = 0;

    for (int l = 0; l < LSEQ; l++) {
        u64 acc[4][4];
        #pragma unroll
        for (int t4 = 0; t4 < 4; t4++) {
            int g0 = t4 * 128 + u0;
            ulonglong2 b0 = *(const ulonglong2*)&sm->sbias[g0];
            ulonglong2 b1 = *(const ulonglong2*)&sm->sbias[g0 + 4];
            acc[t4][0] = b0.x; acc[t4][1] = b0.y;
            acc[t4][2] = b1.x; acc[t4][3] = b1.y;
        }

        if (l == 0) mbar_wait(mbR, 0);
        gemm_chunk(sm->rbuf, sm->h2, 0, 32, r, u0, acc);               // R0

        mbar_wait(mb0, ph0); ph0 ^= 1;
        gemm_chunk(sm->sbuf[0], sm->h2, 64, CHUNK_K, r, u0, acc);      // c0
        __syncthreads();
        if (tid == 0) { mbar_expect_tx(mb0, CHUNK_B);
                        bulk_copy(Wt + 96 * GATES, sm->sbuf[0], CHUNK_B, mb0); }

        mbar_wait(mb1, ph1); ph1 ^= 1;
        gemm_chunk(sm->sbuf[1], sm->h2, 80, CHUNK_K, r, u0, acc);      // c1
        __syncthreads();
        if (tid == 0) { mbar_expect_tx(mb1, CHUNK_B);
                        bulk_copy(Wt + 112 * GATES, sm->sbuf[1], CHUNK_B, mb1); }

        gemm_chunk(sm->rbuf + 32 * GATES, sm->h2, 32, 32, r, u0, acc); // R1

        mbar_wait(mb0, ph0); ph0 ^= 1;
        gemm_chunk(sm->sbuf[0], sm->h2, 96, CHUNK_K, r, u0, acc);      // c2
        __syncthreads();
        if (tid == 0 && l < LSEQ - 1) { mbar_expect_tx(mb0, CHUNK_B);
                        bulk_copy(Wt + 64 * GATES, sm->sbuf[0], CHUNK_B, mb0); }

        mbar_wait(mb1, ph1); ph1 ^= 1;
        gemm_chunk(sm->sbuf[1], sm->h2, 112, CHUNK_K, r, u0, acc);     // c3
        __syncthreads();
        if (tid == 0 && l < LSEQ - 1) { mbar_expect_tx(mb1, CHUNK_B);
                        bulk_copy(Wt + 80 * GATES, sm->sbuf[1], CHUNK_B, mb1); }

        #pragma unroll
        for (int pp = 0; pp < 4; pp++) {
            float i0, i1, f0, f1, g0, g1, o0, o1;
            unpack2(acc[0][pp], i0, i1);
            unpack2(acc[1][pp], f0, f1);
            unpack2(acc[2][pp], g0, g1);
            unpack2(acc[3][pp], o0, o1);
            int j = 2 * pp;
            c[j]      = fsig(f0) * c[j]     + fsig(i0) * ftanhf(g0);
            hn[j]     = fsig(o0) * ftanhf(c[j]);
            c[j + 1]  = fsig(f1) * c[j + 1] + fsig(i1) * ftanhf(g1);
            hn[j + 1] = fsig(o1) * ftanhf(c[j + 1]);
        }

        float part = 0.f;
        #pragma unroll
        for (int j = 0; j < 8; j++) part += hn[j] * wout8[j];
        part += __shfl_xor_sync(0xffffffffu, part, 16);
        #pragma unroll
        for (int j = 0; j < 8; j++)
            *(u64*)&sm->h2[u0 + j][2 * r] = pack2(hn[j], hn[j]);
        if (gh == 0) sm->sp[w][r] = part;
        __syncthreads();
        if (w == 0 && gh == 0) {
            float O = ob;
            #pragma unroll
            for (int ww = 0; ww < 8; ww++) O += sm->sp[ww][r];
            if (l < LSEQ - 1) out[(b_row * (LSEQ - 1) + l) * NVAR + n] = O;
            else              out[PRED_OFF + b_row * NVAR + n] = O;
        }
    }
}

// ---------------- launch ----------------
extern "C" void kernel_launch(void* const* d_in, const int* in_sizes, int n_in,
                              void* d_out, int out_size) {
    (void)in_sizes; (void)n_in; (void)out_size;
    const float* X        = (const float*)d_in[0];
    const float* enc_Wih  = (const float*)d_in[1];
    const float* enc_Whh  = (const float*)d_in[2];
    const float* enc_bih  = (const float*)d_in[3];
    const float* enc_bhh  = (const float*)d_in[4];
    const float* pool_w   = (const float*)d_in[5];
    const float* pool_b   = (const float*)d_in[6];
    const float* Wqkv     = (const float*)d_in[7];
    const float* bqkv     = (const float*)d_in[8];
    const float* Wo       = (const float*)d_in[9];
    const float* bo       = (const float*)d_in[10];
    const float* dec_ih_W = (const float*)d_in[11];
    const float* dec_ih_b = (const float*)d_in[12];
    const float* dec_ic_W = (const float*)d_in[13];
    const float* dec_ic_b = (const float*)d_in[14];
    const float* dec_Whh  = (const float*)d_in[16];
    const float* dec_bih  = (const float*)d_in[17];
    const float* dec_bhh  = (const float*)d_in[18];
    const float* dec_out_W= (const float*)d_in[19];
    const float* dec_out_b= (const float*)d_in[20];
    float* out = (float*)d_out;

    static int attr_set = 0;
    if (!attr_set) {
        cudaFuncSetAttribute(mhsa_kernel, cudaFuncAttributeMaxDynamicSharedMemorySize, 66688);
        cudaFuncSetAttribute(enc_kernel,  cudaFuncAttributeMaxDynamicSharedMemorySize, SMEM_BYTES);
        cudaFuncSetAttribute(dec_kernel,  cudaFuncAttributeMaxDynamicSharedMemorySize, SMEM_BYTES);
        attr_set = 1;
    }

    float *pWtEnc, *pWtDec, *pWtIH, *pWtIC, *pWqkvT;
    cudaGetSymbolAddress((void**)&pWtEnc, g_WtEnc);
    cudaGetSymbolAddress((void**)&pWtDec, g_WtDec);
    cudaGetSymbolAddress((void**)&pWtIH,  g_WtIH);
    cudaGetSymbolAddress((void**)&pWtIC,  g_WtIC);
    cudaGetSymbolAddress((void**)&pWqkvT, g_WqkvT);

    dim3 tb(32, 8);
    transpose_kernel<<<dim3(4, 16, 32), tb>>>(enc_Whh,  pWtEnc, 512, 128);
    transpose_kernel<<<dim3(4, 16, 32), tb>>>(dec_Whh,  pWtDec, 512, 128);
    transpose_kernel<<<dim3(4,  4, 32), tb>>>(dec_ih_W, pWtIH,  128, 128);
    transpose_kernel<<<dim3(4,  4, 32), tb>>>(dec_ic_W, pWtIC,  128, 128);
    transpose_kernel<<<dim3(4, 12,  1), tb>>>(Wqkv,     pWqkvT, 384, 128);

    enc_kernel<<<dim3(PSPLIT, NVAR), 256, SMEM_BYTES>>>(X, enc_Wih, enc_bih, enc_bhh,
                                                        pool_w, pool_b);
    mhsa_kernel<<<BATCH, 128, 66688>>>(bqkv, Wo, bo, out);
    dec_kernel<<<dim3(PSPLIT, NVAR), 256, SMEM_BYTES>>>(dec_ih_b, dec_ic_b, dec_bih, dec_bhh,
                                                        dec_out_W, dec_out_b, out);
}